// round 13
// baseline (speedup 1.0000x reference)
#include <cuda_runtime.h>
#include <cuda_bf16.h>
#include <cstdint>

// ---------------- scratch (device globals; no runtime allocs) ---------------
__device__ float d_xn [16777216];   // LN(x) tf32; later reused as g buffer
__device__ float d_xfn[  786432];   // LN(xf) tf32
__device__ float d_q  [16777216];   // q (tf32)
__device__ float d_k  [ 1048576];   // k (tf32)
__device__ float d_v  [ 1048576];   // v (tf32)
__device__ float d_y  [16777216];   // attention output
__device__ float d_eo [    8192];   // emb_out (scale|shift) fp32
__device__ float d_se [    4096];   // silu(emb)
__device__ float d_Wk [  786432];   // tf32 copies (K-major) for k/v SIMT gemm
__device__ float d_Wv [  786432];
__device__ float d_WqT[ 1048576];   // tf32, transposed [N][K] for big GEMM
__device__ float d_WoT[ 1048576];

// ---------------- helpers ----------------
__device__ __forceinline__ float tf32r(float x) {
    uint32_t u; asm volatile("cvt.rna.tf32.f32 %0, %1;" : "=r"(u) : "f"(x));
    return __uint_as_float(u);
}
__device__ __forceinline__ float silu_f(float x) { return x / (1.f + __expf(-x)); }
__device__ __forceinline__ void cp_async16(void* smem, const void* gmem) {
    uint32_t s = (uint32_t)__cvta_generic_to_shared(smem);
    asm volatile("cp.async.cg.shared.global [%0], [%1], 16;\n" :: "r"(s), "l"(gmem));
}
__device__ __forceinline__ void cp_commit() { asm volatile("cp.async.commit_group;\n" ::); }
template<int NN> __device__ __forceinline__ void cp_wait() {
    asm volatile("cp.async.wait_group %0;\n" :: "n"(NN));
}
__device__ __forceinline__ uint32_t s2u(const void* p) {
    uint32_t a;
    asm("{ .reg .u64 t; cvta.to.shared.u64 t, %1; cvt.u32.u64 %0, t; }" : "=r"(a) : "l"(p));
    return a;
}
__device__ __forceinline__ void mma_tf32(float* d, const float* a, const float* b) {
    const uint32_t* A = reinterpret_cast<const uint32_t*>(a);
    const uint32_t* B = reinterpret_cast<const uint32_t*>(b);
    asm volatile(
        "mma.sync.aligned.m16n8k8.row.col.f32.tf32.tf32.f32 "
        "{%0,%1,%2,%3}, {%4,%5,%6,%7}, {%8,%9}, {%0,%1,%2,%3};\n"
        : "+f"(d[0]), "+f"(d[1]), "+f"(d[2]), "+f"(d[3])
        : "r"(A[0]), "r"(A[1]), "r"(A[2]), "r"(A[3]), "r"(B[0]), "r"(B[1]));
}
__device__ __forceinline__ void mma_tf32_u(float* d, const uint32_t* a, uint32_t b0, uint32_t b1) {
    asm volatile(
        "mma.sync.aligned.m16n8k8.row.col.f32.tf32.tf32.f32 "
        "{%0,%1,%2,%3}, {%4,%5,%6,%7}, {%8,%9}, {%0,%1,%2,%3};\n"
        : "+f"(d[0]), "+f"(d[1]), "+f"(d[2]), "+f"(d[3])
        : "r"(a[0]), "r"(a[1]), "r"(a[2]), "r"(a[3]), "r"(b0), "r"(b1));
}
__device__ __forceinline__ void ldsm4(uint32_t* r, uint32_t addr) {
    asm volatile("ldmatrix.sync.aligned.m8n8.x4.shared.b16 {%0,%1,%2,%3}, [%4];"
                 : "=r"(r[0]), "=r"(r[1]), "=r"(r[2]), "=r"(r[3]) : "r"(addr));
}

// ---------------- big tf32 GEMM via ldmatrix ----------------
// C[M,1024] = A[M,1024] @ BT[N=1024, K=1024]^T (+bias)(+res)(tf32 round opt)
// A row-major K-contig, BT row-major K-contig (pre-transposed weights).
// 128x128 CTA tile, 4 warps of 64x64, BK=32, 2-stage cp.async.
__global__ __launch_bounds__(128)
void gemm_big_kernel(const float* __restrict__ A, const float* __restrict__ BT,
                     const float* __restrict__ bias, const float* __restrict__ res,
                     float* __restrict__ C, int roundOut)
{
    extern __shared__ __align__(16) float sm[];
    float* As = sm;                       // [2][128][36]
    float* Bs = sm + 2 * 128 * 36;        // [2][128][36]
    constexpr int RS = 36;                // row stride (floats)
    constexpr int SS = 128 * RS;          // stage stride (floats)

    const int tid = threadIdx.x, warp = tid >> 5, lane = tid & 31;
    const int wm = warp & 1, wn = warp >> 1;          // 2x2 warp grid
    const int gid = lane >> 2, tig = lane & 3;
    const int blockM = blockIdx.y * 128, blockN = blockIdx.x * 128;

    const float* Ag0 = A  + (long long)(blockM + tid) * 1024;
    const float* Bg0 = BT + (long long)(blockN + tid) * 1024;

    auto load = [&](int kt, int s) {
        const float* Ag = Ag0 + kt * 32;
        const float* Bg = Bg0 + kt * 32;
        float* Ar = As + s * SS + tid * RS;
        float* Br = Bs + s * SS + tid * RS;
        #pragma unroll
        for (int c = 0; c < 8; c++) {
            cp_async16(Ar + c * 4, Ag + c * 4);
            cp_async16(Br + c * 4, Bg + c * 4);
        }
        cp_commit();
    };

    // ldmatrix lane addressing: matrices 0/1 = rows 0-7/8-15 (bytes +0),
    // matrices 2/3 = rows 0-7/8-15 (bytes +16)
    const int fr  = ((lane >> 3) & 1) * 8 + (lane & 7);
    const int fcb = (lane >> 4) * 16;
    uint32_t aAddr[4], bAddr[4];
    #pragma unroll
    for (int mi = 0; mi < 4; mi++)
        aAddr[mi] = s2u(As + (wm * 64 + mi * 16 + fr) * RS) + fcb;
    #pragma unroll
    for (int nj = 0; nj < 4; nj++)
        bAddr[nj] = s2u(Bs + (wn * 64 + nj * 16 + fr) * RS) + fcb;

    float acc[4][8][4];
    #pragma unroll
    for (int mi = 0; mi < 4; mi++)
        #pragma unroll
        for (int nj = 0; nj < 8; nj++)
            #pragma unroll
            for (int r = 0; r < 4; r++) acc[mi][nj][r] = 0.f;

    load(0, 0);
    load(1, 1);

    for (int kt = 0; kt < 32; kt++) {
        const int s = kt & 1;
        if (kt + 1 < 32) cp_wait<1>(); else cp_wait<0>();
        __syncthreads();

        const uint32_t so = (uint32_t)(s * SS * 4);
        #pragma unroll
        for (int ks = 0; ks < 4; ks++) {
            uint32_t af[4][4], bf[4][4];
            #pragma unroll
            for (int mi = 0; mi < 4; mi++) ldsm4(af[mi], aAddr[mi] + so + ks * 32);
            #pragma unroll
            for (int nj = 0; nj < 4; nj++) ldsm4(bf[nj], bAddr[nj] + so + ks * 32);
            #pragma unroll
            for (int mi = 0; mi < 4; mi++) {
                #pragma unroll
                for (int n8 = 0; n8 < 8; n8++) {
                    const int g = n8 >> 1, p = n8 & 1;
                    mma_tf32_u(acc[mi][n8], af[mi], bf[g][p], bf[g][2 + p]);
                }
            }
        }
        __syncthreads();
        if (kt + 2 < 32) load(kt + 2, s);
    }

    // epilogue
    #pragma unroll
    for (int mi = 0; mi < 4; mi++) {
        #pragma unroll
        for (int nj = 0; nj < 8; nj++) {
            const int gr0 = blockM + wm * 64 + mi * 16 + gid;
            const int gc  = blockN + wn * 64 + nj * 8 + tig * 2;
            const float bx = bias[gc], by = bias[gc + 1];
            #pragma unroll
            for (int half = 0; half < 2; half++) {
                const int gr = gr0 + half * 8;
                float v0 = acc[mi][nj][half * 2 + 0] + bx;
                float v1 = acc[mi][nj][half * 2 + 1] + by;
                const long long off = (long long)gr * 1024 + gc;
                if (res) { v0 += res[off]; v1 += res[off + 1]; }
                if (roundOut) { v0 = tf32r(v0); v1 = tf32r(v1); }
                float2 o; o.x = v0; o.y = v1;
                *reinterpret_cast<float2*>(C + off) = o;
            }
        }
    }
}

// ---------------- generic batched-strided tf32 GEMM (k/v proj) --------------
template<int BM, int BN, int WM, int WN>
__global__ __launch_bounds__(256)
void gemm_tf32_kernel(const float* __restrict__ A, const float* __restrict__ B,
                      float* __restrict__ C, const float* __restrict__ bias,
                      const float* __restrict__ res,
                      int M, int N, int K, int lda, int ldb, int ldc,
                      long long sAo, long long sAi, long long sBo, long long sBi,
                      long long sCo, long long sCi, int nInner, int roundOut)
{
    constexpr int BK = 16;
    constexpr int WTM = BM / WM, WTN = BN / WN;
    constexpr int MI = WTM / 16, NI = WTN / 8;

    __shared__ float As[2][BM][BK + 4];
    __shared__ float Bs[2][BK][BN + 8];

    const int z = blockIdx.z;
    const int outer = z / nInner, inner = z - outer * nInner;
    A += outer * sAo + inner * sAi;
    B += outer * sBo + inner * sBi;
    C += outer * sCo + inner * sCi;
    if (res) res += outer * sCo + inner * sCi;

    const int tid = threadIdx.x;
    const int warp = tid >> 5, lane = tid & 31;
    const int wm = warp % WM, wn = warp / WM;
    const int gid = lane >> 2, tig = lane & 3;
    const int blockM = blockIdx.y * BM, blockN = blockIdx.x * BN;

    const int a_row = tid >> 2;
    const int a_col = (tid & 3) << 2;
    constexpr int B_COLS4 = BN / 4;
    constexpr int B_RPP = 256 / B_COLS4;
    constexpr int B_PASSES = BK / B_RPP;
    const int b_row = tid / B_COLS4;
    const int b_col = (tid % B_COLS4) << 2;

    const float* Ab = A + (long long)blockM * lda;
    const float* Bb = B + blockN;

    auto loadStage = [&](int kt, int s) {
        const float* Ag = Ab + kt * BK;
        #pragma unroll
        for (int p = 0; p < 2; p++) {
            int rr = a_row + p * 64;
            cp_async16(&As[s][rr][a_col], Ag + (long long)rr * lda + a_col);
        }
        const float* Bg = Bb + (long long)(kt * BK) * ldb;
        #pragma unroll
        for (int p = 0; p < B_PASSES; p++) {
            int rr = b_row + p * B_RPP;
            cp_async16(&Bs[s][rr][b_col], Bg + (long long)rr * ldb + b_col);
        }
        cp_commit();
    };

    float acc[MI][NI][4];
    #pragma unroll
    for (int mi = 0; mi < MI; mi++)
        #pragma unroll
        for (int ni = 0; ni < NI; ni++)
            #pragma unroll
            for (int rr = 0; rr < 4; rr++) acc[mi][ni][rr] = 0.f;

    const int KT = K / BK;
    const int wrow = wm * WTM, wcol = wn * WTN;

    loadStage(0, 0);
    for (int kt = 0; kt < KT; kt++) {
        const int s = kt & 1;
        if (kt + 1 < KT) { loadStage(kt + 1, s ^ 1); cp_wait<1>(); }
        else             { cp_wait<0>(); }
        __syncthreads();

        #pragma unroll
        for (int ks = 0; ks < 2; ks++) {
            float af[MI][4], bf[NI][2];
            #pragma unroll
            for (int mi = 0; mi < MI; mi++) {
                const int r0 = wrow + mi * 16 + gid, c0 = ks * 8 + tig;
                af[mi][0] = As[s][r0    ][c0    ];
                af[mi][1] = As[s][r0 + 8][c0    ];
                af[mi][2] = As[s][r0    ][c0 + 4];
                af[mi][3] = As[s][r0 + 8][c0 + 4];
            }
            #pragma unroll
            for (int ni = 0; ni < NI; ni++) {
                const int c0 = wcol + ni * 8 + gid, r0 = ks * 8 + tig;
                bf[ni][0] = Bs[s][r0    ][c0];
                bf[ni][1] = Bs[s][r0 + 4][c0];
            }
            #pragma unroll
            for (int mi = 0; mi < MI; mi++)
                #pragma unroll
                for (int ni = 0; ni < NI; ni++)
                    mma_tf32(acc[mi][ni], af[mi], bf[ni]);
        }
        __syncthreads();
    }

    #pragma unroll
    for (int mi = 0; mi < MI; mi++)
        #pragma unroll
        for (int ni = 0; ni < NI; ni++) {
            const int gr0 = blockM + wrow + mi * 16 + gid;
            const int gc  = blockN + wcol + ni * 8 + tig * 2;
            float bx = 0.f, by = 0.f;
            if (bias) { bx = bias[gc]; by = bias[gc + 1]; }
            #pragma unroll
            for (int half = 0; half < 2; half++) {
                const int gr = gr0 + half * 8;
                float v0 = acc[mi][ni][half * 2 + 0] + bx;
                float v1 = acc[mi][ni][half * 2 + 1] + by;
                const long long off = (long long)gr * ldc + gc;
                if (res) { v0 += res[off]; v1 += res[off + 1]; }
                if (roundOut) { v0 = tf32r(v0); v1 = tf32r(v1); }
                float2 o; o.x = v0; o.y = v1;
                *reinterpret_cast<float2*>(C + off) = o;
            }
        }
}

// ---------------- fused flash cross-attention (proven) ----------------
__global__ __launch_bounds__(256)
void flash_kernel(const float* __restrict__ q, const float* __restrict__ k,
                  const float* __restrict__ v, float* __restrict__ y)
{
    extern __shared__ float smf[];
    float* Qs = smf;
    float* Ks = Qs + 128 * 68;
    float* Vs = Ks + 128 * 68;
    float* Ps = Vs + 128 * 68;

    const int tb = blockIdx.x;
    const int bh = blockIdx.y;
    const int b = bh >> 4, h = bh & 15;
    const int tid = threadIdx.x, warp = tid >> 5, lane = tid & 31;
    const int gid = lane >> 2, tig = lane & 3;
    const int wrow = warp * 16;

    const float* qg = q + ((long long)(b * 4096 + tb * 128)) * 1024 + h * 64;
    const float* kg = k + ((long long)(b * 256)) * 1024 + h * 64;
    const float* vg = v + ((long long)(b * 256)) * 1024 + h * 64;

    const int lr = tid >> 4;
    const int lc = (tid & 15) << 2;

    #pragma unroll
    for (int p = 0; p < 8; p++)
        cp_async16(&Qs[(lr + p * 16) * 68 + lc], qg + (long long)(lr + p * 16) * 1024 + lc);
    #pragma unroll
    for (int p = 0; p < 8; p++)
        cp_async16(&Ks[(lr + p * 16) * 68 + lc], kg + (long long)(lr + p * 16) * 1024 + lc);
    #pragma unroll
    for (int p = 0; p < 8; p++)
        cp_async16(&Vs[(lr + p * 16) * 68 + lc], vg + (long long)(lr + p * 16) * 1024 + lc);
    cp_commit();

    float oacc[8][4];
    #pragma unroll
    for (int i = 0; i < 8; i++) { oacc[i][0] = oacc[i][1] = oacc[i][2] = oacc[i][3] = 0.f; }
    float m0 = -1e30f, m1 = -1e30f, l0 = 0.f, l1 = 0.f;

    #pragma unroll
    for (int kb = 0; kb < 2; kb++) {
        cp_wait<0>();
        __syncthreads();

        float sacc[16][4];
        #pragma unroll
        for (int i = 0; i < 16; i++) { sacc[i][0] = sacc[i][1] = sacc[i][2] = sacc[i][3] = 0.f; }
        #pragma unroll
        for (int ks = 0; ks < 8; ks++) {
            float a[4];
            a[0] = Qs[(wrow + gid    ) * 68 + ks * 8 + tig    ];
            a[1] = Qs[(wrow + gid + 8) * 68 + ks * 8 + tig    ];
            a[2] = Qs[(wrow + gid    ) * 68 + ks * 8 + tig + 4];
            a[3] = Qs[(wrow + gid + 8) * 68 + ks * 8 + tig + 4];
            #pragma unroll
            for (int ni = 0; ni < 16; ni++) {
                float bb[2];
                bb[0] = Ks[(ni * 8 + gid) * 68 + ks * 8 + tig    ];
                bb[1] = Ks[(ni * 8 + gid) * 68 + ks * 8 + tig + 4];
                mma_tf32(sacc[ni], a, bb);
            }
        }

        float rm0 = -1e30f, rm1 = -1e30f;
        #pragma unroll
        for (int ni = 0; ni < 16; ni++) {
            sacc[ni][0] *= 0.125f; sacc[ni][1] *= 0.125f;
            sacc[ni][2] *= 0.125f; sacc[ni][3] *= 0.125f;
            rm0 = fmaxf(rm0, fmaxf(sacc[ni][0], sacc[ni][1]));
            rm1 = fmaxf(rm1, fmaxf(sacc[ni][2], sacc[ni][3]));
        }
        rm0 = fmaxf(rm0, __shfl_xor_sync(0xffffffffu, rm0, 1));
        rm0 = fmaxf(rm0, __shfl_xor_sync(0xffffffffu, rm0, 2));
        rm1 = fmaxf(rm1, __shfl_xor_sync(0xffffffffu, rm1, 1));
        rm1 = fmaxf(rm1, __shfl_xor_sync(0xffffffffu, rm1, 2));
        const float mn0 = fmaxf(m0, rm0), mn1 = fmaxf(m1, rm1);
        const float al0 = __expf(m0 - mn0), al1 = __expf(m1 - mn1);
        float ps0 = 0.f, ps1 = 0.f;
        #pragma unroll
        for (int ni = 0; ni < 16; ni++) {
            float p00 = __expf(sacc[ni][0] - mn0);
            float p01 = __expf(sacc[ni][1] - mn0);
            float p10 = __expf(sacc[ni][2] - mn1);
            float p11 = __expf(sacc[ni][3] - mn1);
            ps0 += p00 + p01; ps1 += p10 + p11;
            float2 w0; w0.x = tf32r(p00); w0.y = tf32r(p01);
            float2 w1; w1.x = tf32r(p10); w1.y = tf32r(p11);
            *reinterpret_cast<float2*>(&Ps[(wrow + gid    ) * 132 + ni * 8 + tig * 2]) = w0;
            *reinterpret_cast<float2*>(&Ps[(wrow + gid + 8) * 132 + ni * 8 + tig * 2]) = w1;
        }
        ps0 += __shfl_xor_sync(0xffffffffu, ps0, 1);
        ps0 += __shfl_xor_sync(0xffffffffu, ps0, 2);
        ps1 += __shfl_xor_sync(0xffffffffu, ps1, 1);
        ps1 += __shfl_xor_sync(0xffffffffu, ps1, 2);
        l0 = l0 * al0 + ps0;  l1 = l1 * al1 + ps1;
        m0 = mn0;  m1 = mn1;
        #pragma unroll
        for (int i = 0; i < 8; i++) {
            oacc[i][0] *= al0; oacc[i][1] *= al0;
            oacc[i][2] *= al1; oacc[i][3] *= al1;
        }
        __syncthreads();

        if (kb == 0) {
            #pragma unroll
            for (int p = 0; p < 8; p++)
                cp_async16(&Ks[(lr + p * 16) * 68 + lc],
                           kg + (long long)(128 + lr + p * 16) * 1024 + lc);
            cp_commit();
        }

        #pragma unroll
        for (int ks = 0; ks < 16; ks++) {
            float a[4];
            a[0] = Ps[(wrow + gid    ) * 132 + ks * 8 + tig    ];
            a[1] = Ps[(wrow + gid + 8) * 132 + ks * 8 + tig    ];
            a[2] = Ps[(wrow + gid    ) * 132 + ks * 8 + tig + 4];
            a[3] = Ps[(wrow + gid + 8) * 132 + ks * 8 + tig + 4];
            #pragma unroll
            for (int ni = 0; ni < 8; ni++) {
                float bb[2];
                bb[0] = Vs[(ks * 8 + tig    ) * 68 + ni * 8 + gid];
                bb[1] = Vs[(ks * 8 + tig + 4) * 68 + ni * 8 + gid];
                mma_tf32(oacc[ni], a, bb);
            }
        }
        __syncthreads();

        if (kb == 0) {
            #pragma unroll
            for (int p = 0; p < 8; p++)
                cp_async16(&Vs[(lr + p * 16) * 68 + lc],
                           vg + (long long)(128 + lr + p * 16) * 1024 + lc);
            cp_commit();
        }
    }

    const float inv0 = 1.f / l0, inv1 = 1.f / l1;
    float* yg = y + ((long long)(b * 4096 + tb * 128 + wrow)) * 1024 + h * 64;
    #pragma unroll
    for (int ni = 0; ni < 8; ni++) {
        float2 w0; w0.x = oacc[ni][0] * inv0; w0.y = oacc[ni][1] * inv0;
        float2 w1; w1.x = oacc[ni][2] * inv1; w1.y = oacc[ni][3] * inv1;
        *reinterpret_cast<float2*>(&yg[(long long)gid * 1024 + ni * 8 + tig * 2]) = w0;
        *reinterpret_cast<float2*>(&yg[(long long)(gid + 8) * 1024 + ni * 8 + tig * 2]) = w1;
    }
}

// ---------------- LayerNorm (1 block / row) ----------------
__global__ void ln_kernel(const float* __restrict__ X, float* __restrict__ Y,
                          const float* __restrict__ gam, const float* __restrict__ bet,
                          int Dlen, int roundOut)
{
    const int row = blockIdx.x;
    const float4* x4 = reinterpret_cast<const float4*>(X + (long long)row * Dlen);
    float4* y4 = reinterpret_cast<float4*>(Y + (long long)row * Dlen);
    const int nv = Dlen >> 2;
    const int tid = threadIdx.x, lane = tid & 31, warp = tid >> 5;

    float s = 0.f, ss = 0.f;
    for (int i = tid; i < nv; i += 256) {
        float4 v = x4[i];
        s  += v.x + v.y + v.z + v.w;
        ss += v.x*v.x + v.y*v.y + v.z*v.z + v.w*v.w;
    }
    #pragma unroll
    for (int o = 16; o > 0; o >>= 1) {
        s  += __shfl_xor_sync(0xffffffffu, s, o);
        ss += __shfl_xor_sync(0xffffffffu, ss, o);
    }
    __shared__ float rs[8], rss[8], stat[2];
    if (lane == 0) { rs[warp] = s; rss[warp] = ss; }
    __syncthreads();
    if (tid == 0) {
        float ts = 0.f, tss = 0.f;
        #pragma unroll
        for (int w = 0; w < 8; w++) { ts += rs[w]; tss += rss[w]; }
        const float mu = ts / (float)Dlen;
        const float var = tss / (float)Dlen - mu * mu;
        stat[0] = mu; stat[1] = rsqrtf(var + 1e-5f);
    }
    __syncthreads();
    const float mu = stat[0], rstd = stat[1];
    const float4* g4 = reinterpret_cast<const float4*>(gam);
    const float4* b4 = reinterpret_cast<const float4*>(bet);
    for (int i = tid; i < nv; i += 256) {
        float4 v = x4[i], g = g4[i], b = b4[i];
        v.x = (v.x - mu) * rstd * g.x + b.x;
        v.y = (v.y - mu) * rstd * g.y + b.y;
        v.z = (v.z - mu) * rstd * g.z + b.z;
        v.w = (v.w - mu) * rstd * g.w + b.w;
        if (roundOut) { v.x=tf32r(v.x); v.y=tf32r(v.y); v.z=tf32r(v.z); v.w=tf32r(v.w); }
        y4[i] = v;
    }
}

// ---------------- AdaLN modulate + SiLU (row=1024, T=4096) ----------------
__global__ void modulate_kernel(const float* __restrict__ Yin, const float* __restrict__ eo,
                                const float* __restrict__ gam, const float* __restrict__ bet,
                                float* __restrict__ Out)
{
    const int row = blockIdx.x, b = row >> 12;
    const float4* x4 = reinterpret_cast<const float4*>(Yin + (long long)row * 1024);
    float4* o4 = reinterpret_cast<float4*>(Out + (long long)row * 1024);
    const int tid = threadIdx.x, lane = tid & 31, warp = tid >> 5;

    float4 v = x4[tid];
    float s  = v.x + v.y + v.z + v.w;
    float ss = v.x*v.x + v.y*v.y + v.z*v.z + v.w*v.w;
    #pragma unroll
    for (int o = 16; o > 0; o >>= 1) {
        s  += __shfl_xor_sync(0xffffffffu, s, o);
        ss += __shfl_xor_sync(0xffffffffu, ss, o);
    }
    __shared__ float rs[8], rss[8], stat[2];
    if (lane == 0) { rs[warp] = s; rss[warp] = ss; }
    __syncthreads();
    if (tid == 0) {
        float ts = 0.f, tss = 0.f;
        #pragma unroll
        for (int w = 0; w < 8; w++) { ts += rs[w]; tss += rss[w]; }
        const float mu = ts * (1.f / 1024.f);
        const float var = tss * (1.f / 1024.f) - mu * mu;
        stat[0] = mu; stat[1] = rsqrtf(var + 1e-5f);
    }
    __syncthreads();
    const float mu = stat[0], rstd = stat[1];
    const float4 g  = reinterpret_cast<const float4*>(gam)[tid];
    const float4 bb = reinterpret_cast<const float4*>(bet)[tid];
    const float4 sc = reinterpret_cast<const float4*>(eo + b * 2048)[tid];
    const float4 sh = reinterpret_cast<const float4*>(eo + b * 2048 + 1024)[tid];
    float4 o; float h;
    h = ((v.x-mu)*rstd*g.x + bb.x) * (1.f+sc.x) + sh.x; o.x = tf32r(silu_f(h));
    h = ((v.y-mu)*rstd*g.y + bb.y) * (1.f+sc.y) + sh.y; o.y = tf32r(silu_f(h));
    h = ((v.z-mu)*rstd*g.z + bb.z) * (1.f+sc.z) + sh.z; o.z = tf32r(silu_f(h));
    h = ((v.w-mu)*rstd*g.w + bb.w) * (1.f+sc.w) + sh.w; o.w = tf32r(silu_f(h));
    o4[tid] = o;
}

// ---------------- small utility kernels ----------------
__global__ void tf32copy_kernel(const float* __restrict__ s, float* __restrict__ d, int n) {
    int i = blockIdx.x * 256 + threadIdx.x;
    if (i < n) d[i] = tf32r(s[i]);
}
// WT[n][kk] = tf32(W[kk][n]); W is [1024][1024]
__global__ void tf32trans_kernel(const float* __restrict__ W, float* __restrict__ WT) {
    __shared__ float t[32][33];
    const int bn = blockIdx.x * 32, bk = blockIdx.y * 32;
    const int tx = threadIdx.x, ty = threadIdx.y;
    #pragma unroll
    for (int i = ty; i < 32; i += 8)
        t[i][tx] = W[(long long)(bk + i) * 1024 + bn + tx];
    __syncthreads();
    #pragma unroll
    for (int i = ty; i < 32; i += 8)
        WT[(long long)(bn + i) * 1024 + bk + tx] = tf32r(t[tx][i]);
}
__global__ void silu_emb_kernel(const float* __restrict__ e, float* __restrict__ se) {
    int i = blockIdx.x * 256 + threadIdx.x;
    if (i < 4096) se[i] = silu_f(e[i]);
}
__global__ void embgemm_kernel(const float* __restrict__ se, const float* __restrict__ We,
                               const float* __restrict__ be, float* __restrict__ eo)
{
    const int b = blockIdx.y;
    const int j = blockIdx.x * 256 + threadIdx.x;
    const float* s = se + b * 1024;
    float acc = 0.f;
    #pragma unroll 4
    for (int kk = 0; kk < 1024; kk++) acc += s[kk] * We[kk * 2048 + j];
    eo[b * 2048 + j] = acc + be[j];
}

// ---------------- host ----------------
static float* symf(const void* s) { void* p = nullptr; cudaGetSymbolAddress(&p, s); return (float*)p; }

extern "C" void kernel_launch(void* const* d_in, const int* in_sizes, int n_in,
                              void* d_out, int out_size)
{
    const float* x       = (const float*)d_in[0];
    const float* xf      = (const float*)d_in[1];
    const float* emb     = (const float*)d_in[2];
    const float* norm_g  = (const float*)d_in[3];
    const float* norm_b  = (const float*)d_in[4];
    const float* tnorm_g = (const float*)d_in[5];
    const float* tnorm_b = (const float*)d_in[6];
    const float* Wq      = (const float*)d_in[7];
    const float* bq      = (const float*)d_in[8];
    const float* Wk      = (const float*)d_in[9];
    const float* bk      = (const float*)d_in[10];
    const float* Wv      = (const float*)d_in[11];
    const float* bv      = (const float*)d_in[12];
    const float* We      = (const float*)d_in[13];
    const float* be      = (const float*)d_in[14];
    const float* snorm_g = (const float*)d_in[15];
    const float* snorm_b = (const float*)d_in[16];
    const float* Wo      = (const float*)d_in[17];
    const float* bo      = (const float*)d_in[18];
    float* out = (float*)d_out;

    float* xn  = symf(d_xn);  float* xfn = symf(d_xfn);
    float* q   = symf(d_q);   float* kbuf= symf(d_k);
    float* vbuf= symf(d_v);   float* y   = symf(d_y);
    float* eo  = symf(d_eo);  float* se  = symf(d_se);
    float* wk  = symf(d_Wk);  float* wv  = symf(d_Wv);
    float* wqT = symf(d_WqT); float* woT = symf(d_WoT);

    const int FLASH_SMEM = (128 * 68 * 3 + 128 * 132) * 4;   // 172032 B
    cudaFuncSetAttribute(flash_kernel, cudaFuncAttributeMaxDynamicSharedMemorySize, FLASH_SMEM);
    const int BIG_SMEM = 2 * 2 * 128 * 36 * 4;               // 73728 B
    cudaFuncSetAttribute(gemm_big_kernel, cudaFuncAttributeMaxDynamicSharedMemorySize, BIG_SMEM);

    // prep
    ln_kernel<<<16384, 256>>>(x,  xn,  norm_g,  norm_b,  1024, 1);
    ln_kernel<<<1024,  256>>>(xf, xfn, tnorm_g, tnorm_b, 768,  1);
    tf32trans_kernel<<<dim3(32, 32), dim3(32, 8)>>>(Wq, wqT);
    tf32trans_kernel<<<dim3(32, 32), dim3(32, 8)>>>(Wo, woT);
    tf32copy_kernel<<<3072, 256>>>(Wk, wk, 786432);
    tf32copy_kernel<<<3072, 256>>>(Wv, wv, 786432);
    silu_emb_kernel<<<16, 256>>>(emb, se);
    embgemm_kernel<<<dim3(8, 4), 256>>>(se, We, be, eo);

    // q = LN(x)@Wq + bq  (big ldmatrix GEMM, tf32-rounded out)
    gemm_big_kernel<<<dim3(8, 128), 128, BIG_SMEM>>>(xn, wqT, bq, nullptr, q, 1);

    // k,v = LN(xf)@Wk/Wv + b  (SIMT tf32, small)
    gemm_tf32_kernel<128,128,4,2><<<dim3(8, 8, 1), 256>>>(
        xfn, wk, kbuf, bk, nullptr, 1024, 1024, 768, 768, 1024, 1024,
        0, 0, 0, 0, 0, 0, 1, 1);
    gemm_tf32_kernel<128,128,4,2><<<dim3(8, 8, 1), 256>>>(
        xfn, wv, vbuf, bv, nullptr, 1024, 1024, 768, 768, 1024, 1024,
        0, 0, 0, 0, 0, 0, 1, 1);

    // fused attention
    flash_kernel<<<dim3(32, 64), 256, FLASH_SMEM>>>(q, kbuf, vbuf, y);

    // g = tf32(silu(LN(y)*(1+scale)+shift))  (reuse xn)
    modulate_kernel<<<16384, 256>>>(y, eo, snorm_g, snorm_b, xn);

    // out = x + g@Wo + bo  (big ldmatrix GEMM)
    gemm_big_kernel<<<dim3(8, 128), 128, BIG_SMEM>>>(xn, woT, bo, x, out, 0);
}

// round 15
// speedup vs baseline: 1.1105x; 1.1105x over previous
#include <cuda_runtime.h>
#include <cuda_bf16.h>
#include <cstdint>

// ---------------- scratch (device globals; no runtime allocs) ---------------
__device__ float d_xn [16777216];   // LN(x) tf32; later reused as g buffer
__device__ float d_xfn[  786432];   // LN(xf) tf32
__device__ float d_q  [16777216];   // q (tf32)
__device__ float d_k  [ 1048576];   // k (tf32)
__device__ float d_v  [ 1048576];   // v (tf32)
__device__ float d_y  [16777216];   // attention output
__device__ float d_eo [    8192];   // emb_out (scale|shift) fp32
__device__ float d_se [    4096];   // silu(emb)
__device__ float d_Wk [  786432];   // tf32 copies (K-major) for k/v SIMT gemm
__device__ float d_Wv [  786432];
__device__ float d_WqT[ 1048576];   // tf32, transposed [N][K] for big GEMM
__device__ float d_WoT[ 1048576];

// ---------------- helpers ----------------
__device__ __forceinline__ float tf32r(float x) {
    uint32_t u; asm volatile("cvt.rna.tf32.f32 %0, %1;" : "=r"(u) : "f"(x));
    return __uint_as_float(u);
}
__device__ __forceinline__ float silu_f(float x) { return x / (1.f + __expf(-x)); }
__device__ __forceinline__ void cp_async16(void* smem, const void* gmem) {
    uint32_t s = (uint32_t)__cvta_generic_to_shared(smem);
    asm volatile("cp.async.cg.shared.global [%0], [%1], 16;\n" :: "r"(s), "l"(gmem));
}
__device__ __forceinline__ void cp_commit() { asm volatile("cp.async.commit_group;\n" ::); }
template<int NN> __device__ __forceinline__ void cp_wait() {
    asm volatile("cp.async.wait_group %0;\n" :: "n"(NN));
}
__device__ __forceinline__ uint32_t s2u(const void* p) {
    uint32_t a;
    asm("{ .reg .u64 t; cvta.to.shared.u64 t, %1; cvt.u32.u64 %0, t; }" : "=r"(a) : "l"(p));
    return a;
}
__device__ __forceinline__ void mma_tf32(float* d, const float* a, const float* b) {
    const uint32_t* A = reinterpret_cast<const uint32_t*>(a);
    const uint32_t* B = reinterpret_cast<const uint32_t*>(b);
    asm volatile(
        "mma.sync.aligned.m16n8k8.row.col.f32.tf32.tf32.f32 "
        "{%0,%1,%2,%3}, {%4,%5,%6,%7}, {%8,%9}, {%0,%1,%2,%3};\n"
        : "+f"(d[0]), "+f"(d[1]), "+f"(d[2]), "+f"(d[3])
        : "r"(A[0]), "r"(A[1]), "r"(A[2]), "r"(A[3]), "r"(B[0]), "r"(B[1]));
}
__device__ __forceinline__ void mma_tf32_u(float* d, const uint32_t* a, uint32_t b0, uint32_t b1) {
    asm volatile(
        "mma.sync.aligned.m16n8k8.row.col.f32.tf32.tf32.f32 "
        "{%0,%1,%2,%3}, {%4,%5,%6,%7}, {%8,%9}, {%0,%1,%2,%3};\n"
        : "+f"(d[0]), "+f"(d[1]), "+f"(d[2]), "+f"(d[3])
        : "r"(a[0]), "r"(a[1]), "r"(a[2]), "r"(a[3]), "r"(b0), "r"(b1));
}
__device__ __forceinline__ void ldsm4(uint32_t* r, uint32_t addr) {
    asm volatile("ldmatrix.sync.aligned.m8n8.x4.shared.b16 {%0,%1,%2,%3}, [%4];"
                 : "=r"(r[0]), "=r"(r[1]), "=r"(r[2]), "=r"(r[3]) : "r"(addr));
}

// ---------------- big tf32 GEMM via ldmatrix, 256 thr, 3-stage --------------
// C[M,1024] = A[M,1024] @ BT[N=1024,K=1024]^T (+bias)(+res)(opt tf32 round)
// A row-major K-contig; BT row-major K-contig (pre-transposed weights).
// 128x128 CTA tile; 8 warps as 4(m) x 2(n), each 32x64; BK=32.
__global__ __launch_bounds__(256, 2)
void gemm_big_kernel(const float* __restrict__ A, const float* __restrict__ BT,
                     const float* __restrict__ bias, const float* __restrict__ res,
                     float* __restrict__ C, int roundOut)
{
    extern __shared__ __align__(16) float sm[];
    constexpr int RS = 36;            // floats per smem row (144 B)
    constexpr int HS = 128 * RS;      // A-or-B half stage (floats)
    constexpr int SS = 2 * HS;        // full stage (floats) = 36 KB

    const int tid = threadIdx.x, warp = tid >> 5, lane = tid & 31;
    const int wm = warp & 3, wn = warp >> 2;          // 4 x 2 warp grid
    const int gid = lane >> 2, tig = lane & 3;
    const int blockM = blockIdx.y * 128, blockN = blockIdx.x * 128;

    const int lrow = tid >> 1;            // 0..127
    const int lcol = (tid & 1) * 16;      // 0 or 16
    const float* Ag0 = A  + (long long)(blockM + lrow) * 1024 + lcol;
    const float* Bg0 = BT + (long long)(blockN + lrow) * 1024 + lcol;

    auto load = [&](int kt, int s) {
        const float* Ag = Ag0 + kt * 32;
        const float* Bg = Bg0 + kt * 32;
        float* Ar = sm + s * SS +      lrow * RS + lcol;
        float* Br = sm + s * SS + HS + lrow * RS + lcol;
        #pragma unroll
        for (int c = 0; c < 4; c++) {
            cp_async16(Ar + c * 4, Ag + c * 4);
            cp_async16(Br + c * 4, Bg + c * 4);
        }
        cp_commit();
    };

    // ldmatrix lane addressing (mapping proven correct in prior round)
    const int fr  = ((lane >> 3) & 1) * 8 + (lane & 7);
    const int fcb = (lane >> 4) * 16;
    uint32_t aBase[2], bBase[4];
    #pragma unroll
    for (int mi = 0; mi < 2; mi++)
        aBase[mi] = s2u(sm + (wm * 32 + mi * 16 + fr) * RS) + fcb;
    #pragma unroll
    for (int nj = 0; nj < 4; nj++)
        bBase[nj] = s2u(sm + HS + (wn * 64 + nj * 16 + fr) * RS) + fcb;

    float acc[2][8][4];
    #pragma unroll
    for (int mi = 0; mi < 2; mi++)
        #pragma unroll
        for (int n8 = 0; n8 < 8; n8++)
            #pragma unroll
            for (int r = 0; r < 4; r++) acc[mi][n8][r] = 0.f;

    load(0, 0);
    load(1, 1);

    for (int kt = 0; kt < 32; kt++) {
        const int s = kt % 3;
        if (kt + 2 < 32) load(kt + 2, (kt + 2) % 3);  // safe: stage freed by prev-iter sync
        cp_wait<2>();
        __syncthreads();

        const uint32_t so = (uint32_t)(s * SS * 4);
        #pragma unroll
        for (int ks = 0; ks < 4; ks++) {
            uint32_t af[2][4], bf[4][4];
            #pragma unroll
            for (int mi = 0; mi < 2; mi++) ldsm4(af[mi], aBase[mi] + so + ks * 32);
            #pragma unroll
            for (int nj = 0; nj < 4; nj++) ldsm4(bf[nj], bBase[nj] + so + ks * 32);
            #pragma unroll
            for (int mi = 0; mi < 2; mi++) {
                #pragma unroll
                for (int n8 = 0; n8 < 8; n8++) {
                    const int g = n8 >> 1, p = n8 & 1;
                    mma_tf32_u(acc[mi][n8], af[mi], bf[g][p], bf[g][2 + p]);
                }
            }
        }
        __syncthreads();   // stage s consumed; may be overwritten next iter
    }

    // epilogue
    #pragma unroll
    for (int mi = 0; mi < 2; mi++) {
        #pragma unroll
        for (int n8 = 0; n8 < 8; n8++) {
            const int gr0 = blockM + wm * 32 + mi * 16 + gid;
            const int gc  = blockN + wn * 64 + n8 * 8 + tig * 2;
            const float bx = bias[gc], by = bias[gc + 1];
            #pragma unroll
            for (int half = 0; half < 2; half++) {
                const int gr = gr0 + half * 8;
                float v0 = acc[mi][n8][half * 2 + 0] + bx;
                float v1 = acc[mi][n8][half * 2 + 1] + by;
                const long long off = (long long)gr * 1024 + gc;
                if (res) { v0 += res[off]; v1 += res[off + 1]; }
                if (roundOut) { v0 = tf32r(v0); v1 = tf32r(v1); }
                float2 o; o.x = v0; o.y = v1;
                *reinterpret_cast<float2*>(C + off) = o;
            }
        }
    }
}

// ---------------- generic batched-strided tf32 GEMM (k/v proj) --------------
template<int BM, int BN, int WM, int WN>
__global__ __launch_bounds__(256)
void gemm_tf32_kernel(const float* __restrict__ A, const float* __restrict__ B,
                      float* __restrict__ C, const float* __restrict__ bias,
                      const float* __restrict__ res,
                      int M, int N, int K, int lda, int ldb, int ldc,
                      long long sAo, long long sAi, long long sBo, long long sBi,
                      long long sCo, long long sCi, int nInner, int roundOut)
{
    constexpr int BK = 16;
    constexpr int WTM = BM / WM, WTN = BN / WN;
    constexpr int MI = WTM / 16, NI = WTN / 8;

    __shared__ float As[2][BM][BK + 4];
    __shared__ float Bs[2][BK][BN + 8];

    const int z = blockIdx.z;
    const int outer = z / nInner, inner = z - outer * nInner;
    A += outer * sAo + inner * sAi;
    B += outer * sBo + inner * sBi;
    C += outer * sCo + inner * sCi;
    if (res) res += outer * sCo + inner * sCi;

    const int tid = threadIdx.x;
    const int warp = tid >> 5, lane = tid & 31;
    const int wm = warp % WM, wn = warp / WM;
    const int gid = lane >> 2, tig = lane & 3;
    const int blockM = blockIdx.y * BM, blockN = blockIdx.x * BN;

    const int a_row = tid >> 2;
    const int a_col = (tid & 3) << 2;
    constexpr int B_COLS4 = BN / 4;
    constexpr int B_RPP = 256 / B_COLS4;
    constexpr int B_PASSES = BK / B_RPP;
    const int b_row = tid / B_COLS4;
    const int b_col = (tid % B_COLS4) << 2;

    const float* Ab = A + (long long)blockM * lda;
    const float* Bb = B + blockN;

    auto loadStage = [&](int kt, int s) {
        const float* Ag = Ab + kt * BK;
        #pragma unroll
        for (int p = 0; p < 2; p++) {
            int rr = a_row + p * 64;
            cp_async16(&As[s][rr][a_col], Ag + (long long)rr * lda + a_col);
        }
        const float* Bg = Bb + (long long)(kt * BK) * ldb;
        #pragma unroll
        for (int p = 0; p < B_PASSES; p++) {
            int rr = b_row + p * B_RPP;
            cp_async16(&Bs[s][rr][b_col], Bg + (long long)rr * ldb + b_col);
        }
        cp_commit();
    };

    float acc[MI][NI][4];
    #pragma unroll
    for (int mi = 0; mi < MI; mi++)
        #pragma unroll
        for (int ni = 0; ni < NI; ni++)
            #pragma unroll
            for (int rr = 0; rr < 4; rr++) acc[mi][ni][rr] = 0.f;

    const int KT = K / BK;
    const int wrow = wm * WTM, wcol = wn * WTN;

    loadStage(0, 0);
    for (int kt = 0; kt < KT; kt++) {
        const int s = kt & 1;
        if (kt + 1 < KT) { loadStage(kt + 1, s ^ 1); cp_wait<1>(); }
        else             { cp_wait<0>(); }
        __syncthreads();

        #pragma unroll
        for (int ks = 0; ks < 2; ks++) {
            float af[MI][4], bf[NI][2];
            #pragma unroll
            for (int mi = 0; mi < MI; mi++) {
                const int r0 = wrow + mi * 16 + gid, c0 = ks * 8 + tig;
                af[mi][0] = As[s][r0    ][c0    ];
                af[mi][1] = As[s][r0 + 8][c0    ];
                af[mi][2] = As[s][r0    ][c0 + 4];
                af[mi][3] = As[s][r0 + 8][c0 + 4];
            }
            #pragma unroll
            for (int ni = 0; ni < NI; ni++) {
                const int c0 = wcol + ni * 8 + gid, r0 = ks * 8 + tig;
                bf[ni][0] = Bs[s][r0    ][c0];
                bf[ni][1] = Bs[s][r0 + 4][c0];
            }
            #pragma unroll
            for (int mi = 0; mi < MI; mi++)
                #pragma unroll
                for (int ni = 0; ni < NI; ni++)
                    mma_tf32(acc[mi][ni], af[mi], bf[ni]);
        }
        __syncthreads();
    }

    #pragma unroll
    for (int mi = 0; mi < MI; mi++)
        #pragma unroll
        for (int ni = 0; ni < NI; ni++) {
            const int gr0 = blockM + wrow + mi * 16 + gid;
            const int gc  = blockN + wcol + ni * 8 + tig * 2;
            float bx = 0.f, by = 0.f;
            if (bias) { bx = bias[gc]; by = bias[gc + 1]; }
            #pragma unroll
            for (int half = 0; half < 2; half++) {
                const int gr = gr0 + half * 8;
                float v0 = acc[mi][ni][half * 2 + 0] + bx;
                float v1 = acc[mi][ni][half * 2 + 1] + by;
                const long long off = (long long)gr * ldc + gc;
                if (res) { v0 += res[off]; v1 += res[off + 1]; }
                if (roundOut) { v0 = tf32r(v0); v1 = tf32r(v1); }
                float2 o; o.x = v0; o.y = v1;
                *reinterpret_cast<float2*>(C + off) = o;
            }
        }
}

// ---------------- fused flash cross-attention (proven) ----------------
__global__ __launch_bounds__(256)
void flash_kernel(const float* __restrict__ q, const float* __restrict__ k,
                  const float* __restrict__ v, float* __restrict__ y)
{
    extern __shared__ float smf[];
    float* Qs = smf;
    float* Ks = Qs + 128 * 68;
    float* Vs = Ks + 128 * 68;
    float* Ps = Vs + 128 * 68;

    const int tb = blockIdx.x;
    const int bh = blockIdx.y;
    const int b = bh >> 4, h = bh & 15;
    const int tid = threadIdx.x, warp = tid >> 5, lane = tid & 31;
    const int gid = lane >> 2, tig = lane & 3;
    const int wrow = warp * 16;

    const float* qg = q + ((long long)(b * 4096 + tb * 128)) * 1024 + h * 64;
    const float* kg = k + ((long long)(b * 256)) * 1024 + h * 64;
    const float* vg = v + ((long long)(b * 256)) * 1024 + h * 64;

    const int lr = tid >> 4;
    const int lc = (tid & 15) << 2;

    #pragma unroll
    for (int p = 0; p < 8; p++)
        cp_async16(&Qs[(lr + p * 16) * 68 + lc], qg + (long long)(lr + p * 16) * 1024 + lc);
    #pragma unroll
    for (int p = 0; p < 8; p++)
        cp_async16(&Ks[(lr + p * 16) * 68 + lc], kg + (long long)(lr + p * 16) * 1024 + lc);
    #pragma unroll
    for (int p = 0; p < 8; p++)
        cp_async16(&Vs[(lr + p * 16) * 68 + lc], vg + (long long)(lr + p * 16) * 1024 + lc);
    cp_commit();

    float oacc[8][4];
    #pragma unroll
    for (int i = 0; i < 8; i++) { oacc[i][0] = oacc[i][1] = oacc[i][2] = oacc[i][3] = 0.f; }
    float m0 = -1e30f, m1 = -1e30f, l0 = 0.f, l1 = 0.f;

    #pragma unroll
    for (int kb = 0; kb < 2; kb++) {
        cp_wait<0>();
        __syncthreads();

        float sacc[16][4];
        #pragma unroll
        for (int i = 0; i < 16; i++) { sacc[i][0] = sacc[i][1] = sacc[i][2] = sacc[i][3] = 0.f; }
        #pragma unroll
        for (int ks = 0; ks < 8; ks++) {
            float a[4];
            a[0] = Qs[(wrow + gid    ) * 68 + ks * 8 + tig    ];
            a[1] = Qs[(wrow + gid + 8) * 68 + ks * 8 + tig    ];
            a[2] = Qs[(wrow + gid    ) * 68 + ks * 8 + tig + 4];
            a[3] = Qs[(wrow + gid + 8) * 68 + ks * 8 + tig + 4];
            #pragma unroll
            for (int ni = 0; ni < 16; ni++) {
                float bb[2];
                bb[0] = Ks[(ni * 8 + gid) * 68 + ks * 8 + tig    ];
                bb[1] = Ks[(ni * 8 + gid) * 68 + ks * 8 + tig + 4];
                mma_tf32(sacc[ni], a, bb);
            }
        }

        float rm0 = -1e30f, rm1 = -1e30f;
        #pragma unroll
        for (int ni = 0; ni < 16; ni++) {
            sacc[ni][0] *= 0.125f; sacc[ni][1] *= 0.125f;
            sacc[ni][2] *= 0.125f; sacc[ni][3] *= 0.125f;
            rm0 = fmaxf(rm0, fmaxf(sacc[ni][0], sacc[ni][1]));
            rm1 = fmaxf(rm1, fmaxf(sacc[ni][2], sacc[ni][3]));
        }
        rm0 = fmaxf(rm0, __shfl_xor_sync(0xffffffffu, rm0, 1));
        rm0 = fmaxf(rm0, __shfl_xor_sync(0xffffffffu, rm0, 2));
        rm1 = fmaxf(rm1, __shfl_xor_sync(0xffffffffu, rm1, 1));
        rm1 = fmaxf(rm1, __shfl_xor_sync(0xffffffffu, rm1, 2));
        const float mn0 = fmaxf(m0, rm0), mn1 = fmaxf(m1, rm1);
        const float al0 = __expf(m0 - mn0), al1 = __expf(m1 - mn1);
        float ps0 = 0.f, ps1 = 0.f;
        #pragma unroll
        for (int ni = 0; ni < 16; ni++) {
            float p00 = __expf(sacc[ni][0] - mn0);
            float p01 = __expf(sacc[ni][1] - mn0);
            float p10 = __expf(sacc[ni][2] - mn1);
            float p11 = __expf(sacc[ni][3] - mn1);
            ps0 += p00 + p01; ps1 += p10 + p11;
            float2 w0; w0.x = tf32r(p00); w0.y = tf32r(p01);
            float2 w1; w1.x = tf32r(p10); w1.y = tf32r(p11);
            *reinterpret_cast<float2*>(&Ps[(wrow + gid    ) * 132 + ni * 8 + tig * 2]) = w0;
            *reinterpret_cast<float2*>(&Ps[(wrow + gid + 8) * 132 + ni * 8 + tig * 2]) = w1;
        }
        ps0 += __shfl_xor_sync(0xffffffffu, ps0, 1);
        ps0 += __shfl_xor_sync(0xffffffffu, ps0, 2);
        ps1 += __shfl_xor_sync(0xffffffffu, ps1, 1);
        ps1 += __shfl_xor_sync(0xffffffffu, ps1, 2);
        l0 = l0 * al0 + ps0;  l1 = l1 * al1 + ps1;
        m0 = mn0;  m1 = mn1;
        #pragma unroll
        for (int i = 0; i < 8; i++) {
            oacc[i][0] *= al0; oacc[i][1] *= al0;
            oacc[i][2] *= al1; oacc[i][3] *= al1;
        }
        __syncthreads();

        if (kb == 0) {
            #pragma unroll
            for (int p = 0; p < 8; p++)
                cp_async16(&Ks[(lr + p * 16) * 68 + lc],
                           kg + (long long)(128 + lr + p * 16) * 1024 + lc);
            cp_commit();
        }

        #pragma unroll
        for (int ks = 0; ks < 16; ks++) {
            float a[4];
            a[0] = Ps[(wrow + gid    ) * 132 + ks * 8 + tig    ];
            a[1] = Ps[(wrow + gid + 8) * 132 + ks * 8 + tig    ];
            a[2] = Ps[(wrow + gid    ) * 132 + ks * 8 + tig + 4];
            a[3] = Ps[(wrow + gid + 8) * 132 + ks * 8 + tig + 4];
            #pragma unroll
            for (int ni = 0; ni < 8; ni++) {
                float bb[2];
                bb[0] = Vs[(ks * 8 + tig    ) * 68 + ni * 8 + gid];
                bb[1] = Vs[(ks * 8 + tig + 4) * 68 + ni * 8 + gid];
                mma_tf32(oacc[ni], a, bb);
            }
        }
        __syncthreads();

        if (kb == 0) {
            #pragma unroll
            for (int p = 0; p < 8; p++)
                cp_async16(&Vs[(lr + p * 16) * 68 + lc],
                           vg + (long long)(128 + lr + p * 16) * 1024 + lc);
            cp_commit();
        }
    }

    const float inv0 = 1.f / l0, inv1 = 1.f / l1;
    float* yg = y + ((long long)(b * 4096 + tb * 128 + wrow)) * 1024 + h * 64;
    #pragma unroll
    for (int ni = 0; ni < 8; ni++) {
        float2 w0; w0.x = oacc[ni][0] * inv0; w0.y = oacc[ni][1] * inv0;
        float2 w1; w1.x = oacc[ni][2] * inv1; w1.y = oacc[ni][3] * inv1;
        *reinterpret_cast<float2*>(&yg[(long long)gid * 1024 + ni * 8 + tig * 2]) = w0;
        *reinterpret_cast<float2*>(&yg[(long long)(gid + 8) * 1024 + ni * 8 + tig * 2]) = w1;
    }
}

// ---------------- LayerNorm (1 block / row) ----------------
__global__ void ln_kernel(const float* __restrict__ X, float* __restrict__ Y,
                          const float* __restrict__ gam, const float* __restrict__ bet,
                          int Dlen, int roundOut)
{
    const int row = blockIdx.x;
    const float4* x4 = reinterpret_cast<const float4*>(X + (long long)row * Dlen);
    float4* y4 = reinterpret_cast<float4*>(Y + (long long)row * Dlen);
    const int nv = Dlen >> 2;
    const int tid = threadIdx.x, lane = tid & 31, warp = tid >> 5;

    float s = 0.f, ss = 0.f;
    for (int i = tid; i < nv; i += 256) {
        float4 v = x4[i];
        s  += v.x + v.y + v.z + v.w;
        ss += v.x*v.x + v.y*v.y + v.z*v.z + v.w*v.w;
    }
    #pragma unroll
    for (int o = 16; o > 0; o >>= 1) {
        s  += __shfl_xor_sync(0xffffffffu, s, o);
        ss += __shfl_xor_sync(0xffffffffu, ss, o);
    }
    __shared__ float rs[8], rss[8], stat[2];
    if (lane == 0) { rs[warp] = s; rss[warp] = ss; }
    __syncthreads();
    if (tid == 0) {
        float ts = 0.f, tss = 0.f;
        #pragma unroll
        for (int w = 0; w < 8; w++) { ts += rs[w]; tss += rss[w]; }
        const float mu = ts / (float)Dlen;
        const float var = tss / (float)Dlen - mu * mu;
        stat[0] = mu; stat[1] = rsqrtf(var + 1e-5f);
    }
    __syncthreads();
    const float mu = stat[0], rstd = stat[1];
    const float4* g4 = reinterpret_cast<const float4*>(gam);
    const float4* b4 = reinterpret_cast<const float4*>(bet);
    for (int i = tid; i < nv; i += 256) {
        float4 v = x4[i], g = g4[i], b = b4[i];
        v.x = (v.x - mu) * rstd * g.x + b.x;
        v.y = (v.y - mu) * rstd * g.y + b.y;
        v.z = (v.z - mu) * rstd * g.z + b.z;
        v.w = (v.w - mu) * rstd * g.w + b.w;
        if (roundOut) { v.x=tf32r(v.x); v.y=tf32r(v.y); v.z=tf32r(v.z); v.w=tf32r(v.w); }
        y4[i] = v;
    }
}

// ---------------- AdaLN modulate + SiLU (row=1024, T=4096) ----------------
__global__ void modulate_kernel(const float* __restrict__ Yin, const float* __restrict__ eo,
                                const float* __restrict__ gam, const float* __restrict__ bet,
                                float* __restrict__ Out)
{
    const int row = blockIdx.x, b = row >> 12;
    const float4* x4 = reinterpret_cast<const float4*>(Yin + (long long)row * 1024);
    float4* o4 = reinterpret_cast<float4*>(Out + (long long)row * 1024);
    const int tid = threadIdx.x, lane = tid & 31, warp = tid >> 5;

    float4 v = x4[tid];
    float s  = v.x + v.y + v.z + v.w;
    float ss = v.x*v.x + v.y*v.y + v.z*v.z + v.w*v.w;
    #pragma unroll
    for (int o = 16; o > 0; o >>= 1) {
        s  += __shfl_xor_sync(0xffffffffu, s, o);
        ss += __shfl_xor_sync(0xffffffffu, ss, o);
    }
    __shared__ float rs[8], rss[8], stat[2];
    if (lane == 0) { rs[warp] = s; rss[warp] = ss; }
    __syncthreads();
    if (tid == 0) {
        float ts = 0.f, tss = 0.f;
        #pragma unroll
        for (int w = 0; w < 8; w++) { ts += rs[w]; tss += rss[w]; }
        const float mu = ts * (1.f / 1024.f);
        const float var = tss * (1.f / 1024.f) - mu * mu;
        stat[0] = mu; stat[1] = rsqrtf(var + 1e-5f);
    }
    __syncthreads();
    const float mu = stat[0], rstd = stat[1];
    const float4 g  = reinterpret_cast<const float4*>(gam)[tid];
    const float4 bb = reinterpret_cast<const float4*>(bet)[tid];
    const float4 sc = reinterpret_cast<const float4*>(eo + b * 2048)[tid];
    const float4 sh = reinterpret_cast<const float4*>(eo + b * 2048 + 1024)[tid];
    float4 o; float h;
    h = ((v.x-mu)*rstd*g.x + bb.x) * (1.f+sc.x) + sh.x; o.x = tf32r(silu_f(h));
    h = ((v.y-mu)*rstd*g.y + bb.y) * (1.f+sc.y) + sh.y; o.y = tf32r(silu_f(h));
    h = ((v.z-mu)*rstd*g.z + bb.z) * (1.f+sc.z) + sh.z; o.z = tf32r(silu_f(h));
    h = ((v.w-mu)*rstd*g.w + bb.w) * (1.f+sc.w) + sh.w; o.w = tf32r(silu_f(h));
    o4[tid] = o;
}

// ---------------- small utility kernels ----------------
__global__ void tf32copy_kernel(const float* __restrict__ s, float* __restrict__ d, int n) {
    int i = blockIdx.x * 256 + threadIdx.x;
    if (i < n) d[i] = tf32r(s[i]);
}
// WT[n][kk] = tf32(W[kk][n]); W is [1024][1024]
__global__ void tf32trans_kernel(const float* __restrict__ W, float* __restrict__ WT) {
    __shared__ float t[32][33];
    const int bn = blockIdx.x * 32, bk = blockIdx.y * 32;
    const int tx = threadIdx.x, ty = threadIdx.y;
    #pragma unroll
    for (int i = ty; i < 32; i += 8)
        t[i][tx] = W[(long long)(bk + i) * 1024 + bn + tx];
    __syncthreads();
    #pragma unroll
    for (int i = ty; i < 32; i += 8)
        WT[(long long)(bn + i) * 1024 + bk + tx] = tf32r(t[tx][i]);
}
__global__ void silu_emb_kernel(const float* __restrict__ e, float* __restrict__ se) {
    int i = blockIdx.x * 256 + threadIdx.x;
    if (i < 4096) se[i] = silu_f(e[i]);
}
__global__ void embgemm_kernel(const float* __restrict__ se, const float* __restrict__ We,
                               const float* __restrict__ be, float* __restrict__ eo)
{
    const int b = blockIdx.y;
    const int j = blockIdx.x * 256 + threadIdx.x;
    const float* s = se + b * 1024;
    float acc = 0.f;
    #pragma unroll 4
    for (int kk = 0; kk < 1024; kk++) acc += s[kk] * We[kk * 2048 + j];
    eo[b * 2048 + j] = acc + be[j];
}

// ---------------- host ----------------
static float* symf(const void* s) { void* p = nullptr; cudaGetSymbolAddress(&p, s); return (float*)p; }

extern "C" void kernel_launch(void* const* d_in, const int* in_sizes, int n_in,
                              void* d_out, int out_size)
{
    const float* x       = (const float*)d_in[0];
    const float* xf      = (const float*)d_in[1];
    const float* emb     = (const float*)d_in[2];
    const float* norm_g  = (const float*)d_in[3];
    const float* norm_b  = (const float*)d_in[4];
    const float* tnorm_g = (const float*)d_in[5];
    const float* tnorm_b = (const float*)d_in[6];
    const float* Wq      = (const float*)d_in[7];
    const float* bq      = (const float*)d_in[8];
    const float* Wk      = (const float*)d_in[9];
    const float* bk      = (const float*)d_in[10];
    const float* Wv      = (const float*)d_in[11];
    const float* bv      = (const float*)d_in[12];
    const float* We      = (const float*)d_in[13];
    const float* be      = (const float*)d_in[14];
    const float* snorm_g = (const float*)d_in[15];
    const float* snorm_b = (const float*)d_in[16];
    const float* Wo      = (const float*)d_in[17];
    const float* bo      = (const float*)d_in[18];
    float* out = (float*)d_out;

    float* xn  = symf(d_xn);  float* xfn = symf(d_xfn);
    float* q   = symf(d_q);   float* kbuf= symf(d_k);
    float* vbuf= symf(d_v);   float* y   = symf(d_y);
    float* eo  = symf(d_eo);  float* se  = symf(d_se);
    float* wk  = symf(d_Wk);  float* wv  = symf(d_Wv);
    float* wqT = symf(d_WqT); float* woT = symf(d_WoT);

    const int FLASH_SMEM = (128 * 68 * 3 + 128 * 132) * 4;   // 172032 B
    cudaFuncSetAttribute(flash_kernel, cudaFuncAttributeMaxDynamicSharedMemorySize, FLASH_SMEM);
    const int BIG_SMEM = 3 * 2 * 128 * 36 * 4;               // 110592 B (3 stages)
    cudaFuncSetAttribute(gemm_big_kernel, cudaFuncAttributeMaxDynamicSharedMemorySize, BIG_SMEM);

    // prep
    ln_kernel<<<16384, 256>>>(x,  xn,  norm_g,  norm_b,  1024, 1);
    ln_kernel<<<1024,  256>>>(xf, xfn, tnorm_g, tnorm_b, 768,  1);
    tf32trans_kernel<<<dim3(32, 32), dim3(32, 8)>>>(Wq, wqT);
    tf32trans_kernel<<<dim3(32, 32), dim3(32, 8)>>>(Wo, woT);
    tf32copy_kernel<<<3072, 256>>>(Wk, wk, 786432);
    tf32copy_kernel<<<3072, 256>>>(Wv, wv, 786432);
    silu_emb_kernel<<<16, 256>>>(emb, se);
    embgemm_kernel<<<dim3(8, 4), 256>>>(se, We, be, eo);

    // q = LN(x)@Wq + bq  (ldmatrix big GEMM, tf32-rounded out)
    gemm_big_kernel<<<dim3(8, 128), 256, BIG_SMEM>>>(xn, wqT, bq, nullptr, q, 1);

    // k,v = LN(xf)@Wk/Wv + b  (SIMT tf32, small)
    gemm_tf32_kernel<128,128,4,2><<<dim3(8, 8, 1), 256>>>(
        xfn, wk, kbuf, bk, nullptr, 1024, 1024, 768, 768, 1024, 1024,
        0, 0, 0, 0, 0, 0, 1, 1);
    gemm_tf32_kernel<128,128,4,2><<<dim3(8, 8, 1), 256>>>(
        xfn, wv, vbuf, bv, nullptr, 1024, 1024, 768, 768, 1024, 1024,
        0, 0, 0, 0, 0, 0, 1, 1);

    // fused attention
    flash_kernel<<<dim3(32, 64), 256, FLASH_SMEM>>>(q, kbuf, vbuf, y);

    // g = tf32(silu(LN(y)*(1+scale)+shift))  (reuse xn)
    modulate_kernel<<<16384, 256>>>(y, eo, snorm_g, snorm_b, xn);

    // out = x + g@Wo + bo  (ldmatrix big GEMM, fused residual)
    gemm_big_kernel<<<dim3(8, 128), 256, BIG_SMEM>>>(xn, woT, bo, x, out, 0);
}

// round 16
// speedup vs baseline: 1.2886x; 1.1603x over previous
#include <cuda_runtime.h>
#include <cuda_bf16.h>
#include <cstdint>

// ---------------- scratch (device globals; no runtime allocs) ---------------
__device__ float d_xn [16777216];   // LN(x) tf32; later reused as g buffer
__device__ float d_xfn[  786432];   // LN(xf) tf32
__device__ float d_q  [16777216];   // q (tf32)
__device__ float d_k  [ 1048576];   // k (tf32)
__device__ float d_v  [ 1048576];   // v (tf32)
__device__ float d_y  [16777216];   // attention output
__device__ float d_eo [    8192];   // emb_out (scale|shift) fp32
__device__ float d_se [    4096];   // silu(emb)
__device__ float d_Wq [ 1048576];   // tf32 copies (K-major [K][N])
__device__ float d_Wk [  786432];
__device__ float d_Wv [  786432];
__device__ float d_Wo [ 1048576];

// ---------------- helpers ----------------
__device__ __forceinline__ float tf32r(float x) {
    uint32_t u; asm volatile("cvt.rna.tf32.f32 %0, %1;" : "=r"(u) : "f"(x));
    return __uint_as_float(u);
}
__device__ __forceinline__ float silu_f(float x) { return x / (1.f + __expf(-x)); }
__device__ __forceinline__ void cp_async16(void* smem, const void* gmem) {
    uint32_t s = (uint32_t)__cvta_generic_to_shared(smem);
    asm volatile("cp.async.cg.shared.global [%0], [%1], 16;\n" :: "r"(s), "l"(gmem));
}
__device__ __forceinline__ void cp_commit() { asm volatile("cp.async.commit_group;\n" ::); }
template<int NN> __device__ __forceinline__ void cp_wait() {
    asm volatile("cp.async.wait_group %0;\n" :: "n"(NN));
}
__device__ __forceinline__ void mma_tf32(float* d, const float* a, const float* b) {
    const uint32_t* A = reinterpret_cast<const uint32_t*>(a);
    const uint32_t* B = reinterpret_cast<const uint32_t*>(b);
    asm volatile(
        "mma.sync.aligned.m16n8k8.row.col.f32.tf32.tf32.f32 "
        "{%0,%1,%2,%3}, {%4,%5,%6,%7}, {%8,%9}, {%0,%1,%2,%3};\n"
        : "+f"(d[0]), "+f"(d[1]), "+f"(d[2]), "+f"(d[3])
        : "r"(A[0]), "r"(A[1]), "r"(A[2]), "r"(A[3]), "r"(B[0]), "r"(B[1]));
}

// ---------------- generic batched-strided tf32 GEMM (3-stage, 1 barrier) ----
// C = A@B (+bias)(+res), optional tf32-round of outputs.
// A row-major [M,K] lda; B row-major [K,N] ldb. Batch z: outer=z/nInner,
// inner=z%nInner. Requires M%BM==0, N%BN==0, K%16==0, BM==128, KT>=2.
template<int BM, int BN, int WM, int WN>
__global__ __launch_bounds__(256)
void gemm_tf32_kernel(const float* __restrict__ A, const float* __restrict__ B,
                      float* __restrict__ C, const float* __restrict__ bias,
                      const float* __restrict__ res,
                      int M, int N, int K, int lda, int ldb, int ldc,
                      long long sAo, long long sAi, long long sBo, long long sBi,
                      long long sCo, long long sCi, int nInner, int roundOut)
{
    constexpr int BK = 16;
    constexpr int WTM = BM / WM, WTN = BN / WN;
    constexpr int MI = WTM / 16, NI = WTN / 8;
    constexpr int ARS = BK + 4;           // As row stride (20)
    constexpr int BRS = BN + 8;           // Bs row stride
    constexpr int ASZ = BM * ARS;         // per-stage A floats
    constexpr int BSZ = BK * BRS;         // per-stage B floats

    extern __shared__ __align__(16) float dsm[];
    float* AsBase = dsm;                  // 3 stages of A
    float* BsBase = dsm + 3 * ASZ;        // 3 stages of B

    const int z = blockIdx.z;
    const int outer = z / nInner, inner = z - outer * nInner;
    A += outer * sAo + inner * sAi;
    B += outer * sBo + inner * sBi;
    C += outer * sCo + inner * sCi;
    if (res) res += outer * sCo + inner * sCi;

    const int tid = threadIdx.x;
    const int warp = tid >> 5, lane = tid & 31;
    const int wm = warp % WM, wn = warp / WM;
    const int gid = lane >> 2, tig = lane & 3;
    const int blockM = blockIdx.y * BM, blockN = blockIdx.x * BN;

    const int a_row = tid >> 2;
    const int a_col = (tid & 3) << 2;
    constexpr int B_COLS4 = BN / 4;
    constexpr int B_RPP = 256 / B_COLS4;
    constexpr int B_PASSES = BK / B_RPP;
    const int b_row = tid / B_COLS4;
    const int b_col = (tid % B_COLS4) << 2;

    const float* Ab = A + (long long)blockM * lda;
    const float* Bb = B + blockN;

    auto loadStage = [&](int kt, int s) {
        const float* Ag = Ab + kt * BK;
        float* As = AsBase + s * ASZ;
        #pragma unroll
        for (int p = 0; p < 2; p++) {
            int rr = a_row + p * 64;
            cp_async16(As + rr * ARS + a_col, Ag + (long long)rr * lda + a_col);
        }
        const float* Bg = Bb + (long long)(kt * BK) * ldb;
        float* Bs = BsBase + s * BSZ;
        #pragma unroll
        for (int p = 0; p < B_PASSES; p++) {
            int rr = b_row + p * B_RPP;
            cp_async16(Bs + rr * BRS + b_col, Bg + (long long)rr * ldb + b_col);
        }
        cp_commit();
    };

    float acc[MI][NI][4];
    #pragma unroll
    for (int mi = 0; mi < MI; mi++)
        #pragma unroll
        for (int ni = 0; ni < NI; ni++)
            #pragma unroll
            for (int rr = 0; rr < 4; rr++) acc[mi][ni][rr] = 0.f;

    const int KT = K / BK;
    const int wrow = wm * WTM, wcol = wn * WTN;

    loadStage(0, 0);
    loadStage(1, 1);

    for (int kt = 0; kt < KT; kt++) {
        const int s = kt % 3;
        if (kt + 1 < KT) cp_wait<1>(); else cp_wait<0>();
        __syncthreads();
        // safe: stage (kt+2)%3 == (kt-1)%3 was consumed at iter kt-1;
        // every warp passed this iter's barrier, which follows that compute.
        if (kt + 2 < KT) loadStage(kt + 2, (kt + 2) % 3);

        const float* As = AsBase + s * ASZ;
        const float* Bs = BsBase + s * BSZ;
        #pragma unroll
        for (int ks = 0; ks < 2; ks++) {
            float af[MI][4], bf[NI][2];
            #pragma unroll
            for (int mi = 0; mi < MI; mi++) {
                const int r0 = wrow + mi * 16 + gid, c0 = ks * 8 + tig;
                af[mi][0] = As[(r0    ) * ARS + c0    ];
                af[mi][1] = As[(r0 + 8) * ARS + c0    ];
                af[mi][2] = As[(r0    ) * ARS + c0 + 4];
                af[mi][3] = As[(r0 + 8) * ARS + c0 + 4];
            }
            #pragma unroll
            for (int ni = 0; ni < NI; ni++) {
                const int c0 = wcol + ni * 8 + gid, r0 = ks * 8 + tig;
                bf[ni][0] = Bs[(r0    ) * BRS + c0];
                bf[ni][1] = Bs[(r0 + 4) * BRS + c0];
            }
            #pragma unroll
            for (int mi = 0; mi < MI; mi++)
                #pragma unroll
                for (int ni = 0; ni < NI; ni++)
                    mma_tf32(acc[mi][ni], af[mi], bf[ni]);
        }
    }

    #pragma unroll
    for (int mi = 0; mi < MI; mi++)
        #pragma unroll
        for (int ni = 0; ni < NI; ni++) {
            const int gr0 = blockM + wrow + mi * 16 + gid;
            const int gc  = blockN + wcol + ni * 8 + tig * 2;
            float bx = 0.f, by = 0.f;
            if (bias) { bx = bias[gc]; by = bias[gc + 1]; }
            #pragma unroll
            for (int half = 0; half < 2; half++) {
                const int gr = gr0 + half * 8;
                float v0 = acc[mi][ni][half * 2 + 0] + bx;
                float v1 = acc[mi][ni][half * 2 + 1] + by;
                const long long off = (long long)gr * ldc + gc;
                if (res) { v0 += res[off]; v1 += res[off + 1]; }
                if (roundOut) { v0 = tf32r(v0); v1 = tf32r(v1); }
                float2 o; o.x = v0; o.y = v1;
                *reinterpret_cast<float2*>(C + off) = o;
            }
        }
}

// ---------------- fused flash cross-attention (proven) ----------------
__global__ __launch_bounds__(256)
void flash_kernel(const float* __restrict__ q, const float* __restrict__ k,
                  const float* __restrict__ v, float* __restrict__ y)
{
    extern __shared__ float smf[];
    float* Qs = smf;
    float* Ks = Qs + 128 * 68;
    float* Vs = Ks + 128 * 68;
    float* Ps = Vs + 128 * 68;

    const int tb = blockIdx.x;
    const int bh = blockIdx.y;
    const int b = bh >> 4, h = bh & 15;
    const int tid = threadIdx.x, warp = tid >> 5, lane = tid & 31;
    const int gid = lane >> 2, tig = lane & 3;
    const int wrow = warp * 16;

    const float* qg = q + ((long long)(b * 4096 + tb * 128)) * 1024 + h * 64;
    const float* kg = k + ((long long)(b * 256)) * 1024 + h * 64;
    const float* vg = v + ((long long)(b * 256)) * 1024 + h * 64;

    const int lr = tid >> 4;
    const int lc = (tid & 15) << 2;

    #pragma unroll
    for (int p = 0; p < 8; p++)
        cp_async16(&Qs[(lr + p * 16) * 68 + lc], qg + (long long)(lr + p * 16) * 1024 + lc);
    #pragma unroll
    for (int p = 0; p < 8; p++)
        cp_async16(&Ks[(lr + p * 16) * 68 + lc], kg + (long long)(lr + p * 16) * 1024 + lc);
    #pragma unroll
    for (int p = 0; p < 8; p++)
        cp_async16(&Vs[(lr + p * 16) * 68 + lc], vg + (long long)(lr + p * 16) * 1024 + lc);
    cp_commit();

    float oacc[8][4];
    #pragma unroll
    for (int i = 0; i < 8; i++) { oacc[i][0] = oacc[i][1] = oacc[i][2] = oacc[i][3] = 0.f; }
    float m0 = -1e30f, m1 = -1e30f, l0 = 0.f, l1 = 0.f;

    #pragma unroll
    for (int kb = 0; kb < 2; kb++) {
        cp_wait<0>();
        __syncthreads();

        float sacc[16][4];
        #pragma unroll
        for (int i = 0; i < 16; i++) { sacc[i][0] = sacc[i][1] = sacc[i][2] = sacc[i][3] = 0.f; }
        #pragma unroll
        for (int ks = 0; ks < 8; ks++) {
            float a[4];
            a[0] = Qs[(wrow + gid    ) * 68 + ks * 8 + tig    ];
            a[1] = Qs[(wrow + gid + 8) * 68 + ks * 8 + tig    ];
            a[2] = Qs[(wrow + gid    ) * 68 + ks * 8 + tig + 4];
            a[3] = Qs[(wrow + gid + 8) * 68 + ks * 8 + tig + 4];
            #pragma unroll
            for (int ni = 0; ni < 16; ni++) {
                float bb[2];
                bb[0] = Ks[(ni * 8 + gid) * 68 + ks * 8 + tig    ];
                bb[1] = Ks[(ni * 8 + gid) * 68 + ks * 8 + tig + 4];
                mma_tf32(sacc[ni], a, bb);
            }
        }

        float rm0 = -1e30f, rm1 = -1e30f;
        #pragma unroll
        for (int ni = 0; ni < 16; ni++) {
            sacc[ni][0] *= 0.125f; sacc[ni][1] *= 0.125f;
            sacc[ni][2] *= 0.125f; sacc[ni][3] *= 0.125f;
            rm0 = fmaxf(rm0, fmaxf(sacc[ni][0], sacc[ni][1]));
            rm1 = fmaxf(rm1, fmaxf(sacc[ni][2], sacc[ni][3]));
        }
        rm0 = fmaxf(rm0, __shfl_xor_sync(0xffffffffu, rm0, 1));
        rm0 = fmaxf(rm0, __shfl_xor_sync(0xffffffffu, rm0, 2));
        rm1 = fmaxf(rm1, __shfl_xor_sync(0xffffffffu, rm1, 1));
        rm1 = fmaxf(rm1, __shfl_xor_sync(0xffffffffu, rm1, 2));
        const float mn0 = fmaxf(m0, rm0), mn1 = fmaxf(m1, rm1);
        const float al0 = __expf(m0 - mn0), al1 = __expf(m1 - mn1);
        float ps0 = 0.f, ps1 = 0.f;
        #pragma unroll
        for (int ni = 0; ni < 16; ni++) {
            float p00 = __expf(sacc[ni][0] - mn0);
            float p01 = __expf(sacc[ni][1] - mn0);
            float p10 = __expf(sacc[ni][2] - mn1);
            float p11 = __expf(sacc[ni][3] - mn1);
            ps0 += p00 + p01; ps1 += p10 + p11;
            float2 w0; w0.x = tf32r(p00); w0.y = tf32r(p01);
            float2 w1; w1.x = tf32r(p10); w1.y = tf32r(p11);
            *reinterpret_cast<float2*>(&Ps[(wrow + gid    ) * 132 + ni * 8 + tig * 2]) = w0;
            *reinterpret_cast<float2*>(&Ps[(wrow + gid + 8) * 132 + ni * 8 + tig * 2]) = w1;
        }
        ps0 += __shfl_xor_sync(0xffffffffu, ps0, 1);
        ps0 += __shfl_xor_sync(0xffffffffu, ps0, 2);
        ps1 += __shfl_xor_sync(0xffffffffu, ps1, 1);
        ps1 += __shfl_xor_sync(0xffffffffu, ps1, 2);
        l0 = l0 * al0 + ps0;  l1 = l1 * al1 + ps1;
        m0 = mn0;  m1 = mn1;
        #pragma unroll
        for (int i = 0; i < 8; i++) {
            oacc[i][0] *= al0; oacc[i][1] *= al0;
            oacc[i][2] *= al1; oacc[i][3] *= al1;
        }
        __syncthreads();

        if (kb == 0) {
            #pragma unroll
            for (int p = 0; p < 8; p++)
                cp_async16(&Ks[(lr + p * 16) * 68 + lc],
                           kg + (long long)(128 + lr + p * 16) * 1024 + lc);
            cp_commit();
        }

        #pragma unroll
        for (int ks = 0; ks < 16; ks++) {
            float a[4];
            a[0] = Ps[(wrow + gid    ) * 132 + ks * 8 + tig    ];
            a[1] = Ps[(wrow + gid + 8) * 132 + ks * 8 + tig    ];
            a[2] = Ps[(wrow + gid    ) * 132 + ks * 8 + tig + 4];
            a[3] = Ps[(wrow + gid + 8) * 132 + ks * 8 + tig + 4];
            #pragma unroll
            for (int ni = 0; ni < 8; ni++) {
                float bb[2];
                bb[0] = Vs[(ks * 8 + tig    ) * 68 + ni * 8 + gid];
                bb[1] = Vs[(ks * 8 + tig + 4) * 68 + ni * 8 + gid];
                mma_tf32(oacc[ni], a, bb);
            }
        }
        __syncthreads();

        if (kb == 0) {
            #pragma unroll
            for (int p = 0; p < 8; p++)
                cp_async16(&Vs[(lr + p * 16) * 68 + lc],
                           vg + (long long)(128 + lr + p * 16) * 1024 + lc);
            cp_commit();
        }
    }

    const float inv0 = 1.f / l0, inv1 = 1.f / l1;
    float* yg = y + ((long long)(b * 4096 + tb * 128 + wrow)) * 1024 + h * 64;
    #pragma unroll
    for (int ni = 0; ni < 8; ni++) {
        float2 w0; w0.x = oacc[ni][0] * inv0; w0.y = oacc[ni][1] * inv0;
        float2 w1; w1.x = oacc[ni][2] * inv1; w1.y = oacc[ni][3] * inv1;
        *reinterpret_cast<float2*>(&yg[(long long)gid * 1024 + ni * 8 + tig * 2]) = w0;
        *reinterpret_cast<float2*>(&yg[(long long)(gid + 8) * 1024 + ni * 8 + tig * 2]) = w1;
    }
}

// ---------------- LayerNorm (1 block / row) ----------------
__global__ void ln_kernel(const float* __restrict__ X, float* __restrict__ Y,
                          const float* __restrict__ gam, const float* __restrict__ bet,
                          int Dlen, int roundOut)
{
    const int row = blockIdx.x;
    const float4* x4 = reinterpret_cast<const float4*>(X + (long long)row * Dlen);
    float4* y4 = reinterpret_cast<float4*>(Y + (long long)row * Dlen);
    const int nv = Dlen >> 2;
    const int tid = threadIdx.x, lane = tid & 31, warp = tid >> 5;

    float s = 0.f, ss = 0.f;
    for (int i = tid; i < nv; i += 256) {
        float4 v = x4[i];
        s  += v.x + v.y + v.z + v.w;
        ss += v.x*v.x + v.y*v.y + v.z*v.z + v.w*v.w;
    }
    #pragma unroll
    for (int o = 16; o > 0; o >>= 1) {
        s  += __shfl_xor_sync(0xffffffffu, s, o);
        ss += __shfl_xor_sync(0xffffffffu, ss, o);
    }
    __shared__ float rs[8], rss[8], stat[2];
    if (lane == 0) { rs[warp] = s; rss[warp] = ss; }
    __syncthreads();
    if (tid == 0) {
        float ts = 0.f, tss = 0.f;
        #pragma unroll
        for (int w = 0; w < 8; w++) { ts += rs[w]; tss += rss[w]; }
        const float mu = ts / (float)Dlen;
        const float var = tss / (float)Dlen - mu * mu;
        stat[0] = mu; stat[1] = rsqrtf(var + 1e-5f);
    }
    __syncthreads();
    const float mu = stat[0], rstd = stat[1];
    const float4* g4 = reinterpret_cast<const float4*>(gam);
    const float4* b4 = reinterpret_cast<const float4*>(bet);
    for (int i = tid; i < nv; i += 256) {
        float4 v = x4[i], g = g4[i], b = b4[i];
        v.x = (v.x - mu) * rstd * g.x + b.x;
        v.y = (v.y - mu) * rstd * g.y + b.y;
        v.z = (v.z - mu) * rstd * g.z + b.z;
        v.w = (v.w - mu) * rstd * g.w + b.w;
        if (roundOut) { v.x=tf32r(v.x); v.y=tf32r(v.y); v.z=tf32r(v.z); v.w=tf32r(v.w); }
        y4[i] = v;
    }
}

// ---------------- AdaLN modulate + SiLU (row=1024, T=4096) ----------------
__global__ void modulate_kernel(const float* __restrict__ Yin, const float* __restrict__ eo,
                                const float* __restrict__ gam, const float* __restrict__ bet,
                                float* __restrict__ Out)
{
    const int row = blockIdx.x, b = row >> 12;
    const float4* x4 = reinterpret_cast<const float4*>(Yin + (long long)row * 1024);
    float4* o4 = reinterpret_cast<float4*>(Out + (long long)row * 1024);
    const int tid = threadIdx.x, lane = tid & 31, warp = tid >> 5;

    float4 v = x4[tid];
    float s  = v.x + v.y + v.z + v.w;
    float ss = v.x*v.x + v.y*v.y + v.z*v.z + v.w*v.w;
    #pragma unroll
    for (int o = 16; o > 0; o >>= 1) {
        s  += __shfl_xor_sync(0xffffffffu, s, o);
        ss += __shfl_xor_sync(0xffffffffu, ss, o);
    }
    __shared__ float rs[8], rss[8], stat[2];
    if (lane == 0) { rs[warp] = s; rss[warp] = ss; }
    __syncthreads();
    if (tid == 0) {
        float ts = 0.f, tss = 0.f;
        #pragma unroll
        for (int w = 0; w < 8; w++) { ts += rs[w]; tss += rss[w]; }
        const float mu = ts * (1.f / 1024.f);
        const float var = tss * (1.f / 1024.f) - mu * mu;
        stat[0] = mu; stat[1] = rsqrtf(var + 1e-5f);
    }
    __syncthreads();
    const float mu = stat[0], rstd = stat[1];
    const float4 g  = reinterpret_cast<const float4*>(gam)[tid];
    const float4 bb = reinterpret_cast<const float4*>(bet)[tid];
    const float4 sc = reinterpret_cast<const float4*>(eo + b * 2048)[tid];
    const float4 sh = reinterpret_cast<const float4*>(eo + b * 2048 + 1024)[tid];
    float4 o; float h;
    h = ((v.x-mu)*rstd*g.x + bb.x) * (1.f+sc.x) + sh.x; o.x = tf32r(silu_f(h));
    h = ((v.y-mu)*rstd*g.y + bb.y) * (1.f+sc.y) + sh.y; o.y = tf32r(silu_f(h));
    h = ((v.z-mu)*rstd*g.z + bb.z) * (1.f+sc.z) + sh.z; o.z = tf32r(silu_f(h));
    h = ((v.w-mu)*rstd*g.w + bb.w) * (1.f+sc.w) + sh.w; o.w = tf32r(silu_f(h));
    o4[tid] = o;
}

// ---------------- small utility kernels ----------------
__global__ void tf32copy_kernel(const float* __restrict__ s, float* __restrict__ d, int n) {
    int i = blockIdx.x * 256 + threadIdx.x;
    if (i < n) d[i] = tf32r(s[i]);
}
__global__ void silu_emb_kernel(const float* __restrict__ e, float* __restrict__ se) {
    int i = blockIdx.x * 256 + threadIdx.x;
    if (i < 4096) se[i] = silu_f(e[i]);
}
__global__ void embgemm_kernel(const float* __restrict__ se, const float* __restrict__ We,
                               const float* __restrict__ be, float* __restrict__ eo)
{
    const int b = blockIdx.y;
    const int j = blockIdx.x * 256 + threadIdx.x;
    const float* s = se + b * 1024;
    float acc = 0.f;
    #pragma unroll 4
    for (int kk = 0; kk < 1024; kk++) acc += s[kk] * We[kk * 2048 + j];
    eo[b * 2048 + j] = acc + be[j];
}

// ---------------- host ----------------
static float* symf(const void* s) { void* p = nullptr; cudaGetSymbolAddress(&p, s); return (float*)p; }

extern "C" void kernel_launch(void* const* d_in, const int* in_sizes, int n_in,
                              void* d_out, int out_size)
{
    const float* x       = (const float*)d_in[0];
    const float* xf      = (const float*)d_in[1];
    const float* emb     = (const float*)d_in[2];
    const float* norm_g  = (const float*)d_in[3];
    const float* norm_b  = (const float*)d_in[4];
    const float* tnorm_g = (const float*)d_in[5];
    const float* tnorm_b = (const float*)d_in[6];
    const float* Wq      = (const float*)d_in[7];
    const float* bq      = (const float*)d_in[8];
    const float* Wk      = (const float*)d_in[9];
    const float* bk      = (const float*)d_in[10];
    const float* Wv      = (const float*)d_in[11];
    const float* bv      = (const float*)d_in[12];
    const float* We      = (const float*)d_in[13];
    const float* be      = (const float*)d_in[14];
    const float* snorm_g = (const float*)d_in[15];
    const float* snorm_b = (const float*)d_in[16];
    const float* Wo      = (const float*)d_in[17];
    const float* bo      = (const float*)d_in[18];
    float* out = (float*)d_out;

    float* xn  = symf(d_xn);  float* xfn = symf(d_xfn);
    float* q   = symf(d_q);   float* kbuf= symf(d_k);
    float* vbuf= symf(d_v);   float* y   = symf(d_y);
    float* eo  = symf(d_eo);  float* se  = symf(d_se);
    float* wq  = symf(d_Wq);  float* wk  = symf(d_Wk);
    float* wv  = symf(d_Wv);  float* wo  = symf(d_Wo);

    const int FLASH_SMEM = (128 * 68 * 3 + 128 * 132) * 4;   // 172032 B
    cudaFuncSetAttribute(flash_kernel, cudaFuncAttributeMaxDynamicSharedMemorySize, FLASH_SMEM);
    // 3-stage dynamic smem: 3*(128*20 + 16*136)*4 = 56832 B
    const int GEMM_SMEM = 3 * (128 * 20 + 16 * 136) * 4;
    cudaFuncSetAttribute(gemm_tf32_kernel<128,128,4,2>,
                         cudaFuncAttributeMaxDynamicSharedMemorySize, GEMM_SMEM);

    // prep
    ln_kernel<<<16384, 256>>>(x,  xn,  norm_g,  norm_b,  1024, 1);
    ln_kernel<<<1024,  256>>>(xf, xfn, tnorm_g, tnorm_b, 768,  1);
    tf32copy_kernel<<<4096, 256>>>(Wq, wq, 1048576);
    tf32copy_kernel<<<3072, 256>>>(Wk, wk, 786432);
    tf32copy_kernel<<<3072, 256>>>(Wv, wv, 786432);
    tf32copy_kernel<<<4096, 256>>>(Wo, wo, 1048576);
    silu_emb_kernel<<<16, 256>>>(emb, se);
    embgemm_kernel<<<dim3(8, 4), 256>>>(se, We, be, eo);

    // q = LN(x)@Wq + bq   [16384,1024]x[1024,1024]
    gemm_tf32_kernel<128,128,4,2><<<dim3(8, 128, 1), 256, GEMM_SMEM>>>(
        xn, wq, q, bq, nullptr, 16384, 1024, 1024, 1024, 1024, 1024,
        0, 0, 0, 0, 0, 0, 1, 1);
    // k,v = LN(xf)@Wk/Wv + b   [1024,768]x[768,1024]
    gemm_tf32_kernel<128,128,4,2><<<dim3(8, 8, 1), 256, GEMM_SMEM>>>(
        xfn, wk, kbuf, bk, nullptr, 1024, 1024, 768, 768, 1024, 1024,
        0, 0, 0, 0, 0, 0, 1, 1);
    gemm_tf32_kernel<128,128,4,2><<<dim3(8, 8, 1), 256, GEMM_SMEM>>>(
        xfn, wv, vbuf, bv, nullptr, 1024, 1024, 768, 768, 1024, 1024,
        0, 0, 0, 0, 0, 0, 1, 1);

    // fused attention: y = softmax(q k^T / 8) v
    flash_kernel<<<dim3(32, 64), 256, FLASH_SMEM>>>(q, kbuf, vbuf, y);

    // g = tf32(silu(LN(y)*(1+scale)+shift))  (reuse xn)
    modulate_kernel<<<16384, 256>>>(y, eo, snorm_g, snorm_b, xn);

    // out = x + g@Wo + bo
    gemm_tf32_kernel<128,128,4,2><<<dim3(8, 128, 1), 256, GEMM_SMEM>>>(
        xn, wo, out, bo, x, 16384, 1024, 1024, 1024, 1024, 1024,
        0, 0, 0, 0, 0, 0, 1, 0);
}

// round 17
// speedup vs baseline: 1.7127x; 1.3291x over previous
#include <cuda_runtime.h>
#include <cuda_fp16.h>
#include <cstdint>

// ---------------- scratch (device globals; no runtime allocs) ---------------
__device__ __half d_ah [16777216];  // fp16 A for big GEMMs (LN(x), then g)
__device__ __half d_Wqh[ 1048576];  // fp16 Wq^T [N][K]
__device__ __half d_Woh[ 1048576];  // fp16 Wo^T [N][K]
__device__ float d_xfn[  786432];   // LN(xf) tf32
__device__ float d_q  [16777216];   // q (tf32)
__device__ float d_k  [ 1048576];   // k (tf32)
__device__ float d_v  [ 1048576];   // v (tf32)
__device__ float d_y  [16777216];   // attention output
__device__ float d_eo [    8192];   // emb_out (scale|shift) fp32
__device__ float d_se [    4096];   // silu(emb)
__device__ float d_Wk [  786432];   // tf32 copies for k/v SIMT gemm
__device__ float d_Wv [  786432];

// ---------------- helpers ----------------
__device__ __forceinline__ float tf32r(float x) {
    uint32_t u; asm volatile("cvt.rna.tf32.f32 %0, %1;" : "=r"(u) : "f"(x));
    return __uint_as_float(u);
}
__device__ __forceinline__ float silu_f(float x) { return x / (1.f + __expf(-x)); }
__device__ __forceinline__ void cp_async16(void* smem, const void* gmem) {
    uint32_t s = (uint32_t)__cvta_generic_to_shared(smem);
    asm volatile("cp.async.cg.shared.global [%0], [%1], 16;\n" :: "r"(s), "l"(gmem));
}
__device__ __forceinline__ void cp_commit() { asm volatile("cp.async.commit_group;\n" ::); }
template<int NN> __device__ __forceinline__ void cp_wait() {
    asm volatile("cp.async.wait_group %0;\n" :: "n"(NN));
}
__device__ __forceinline__ void mma_tf32(float* d, const float* a, const float* b) {
    const uint32_t* A = reinterpret_cast<const uint32_t*>(a);
    const uint32_t* B = reinterpret_cast<const uint32_t*>(b);
    asm volatile(
        "mma.sync.aligned.m16n8k8.row.col.f32.tf32.tf32.f32 "
        "{%0,%1,%2,%3}, {%4,%5,%6,%7}, {%8,%9}, {%0,%1,%2,%3};\n"
        : "+f"(d[0]), "+f"(d[1]), "+f"(d[2]), "+f"(d[3])
        : "r"(A[0]), "r"(A[1]), "r"(A[2]), "r"(A[3]), "r"(B[0]), "r"(B[1]));
}
__device__ __forceinline__ void mma_f16(float* d, const uint32_t* a, uint32_t b0, uint32_t b1) {
    asm volatile(
        "mma.sync.aligned.m16n8k16.row.col.f32.f16.f16.f32 "
        "{%0,%1,%2,%3}, {%4,%5,%6,%7}, {%8,%9}, {%0,%1,%2,%3};\n"
        : "+f"(d[0]), "+f"(d[1]), "+f"(d[2]), "+f"(d[3])
        : "r"(a[0]), "r"(a[1]), "r"(a[2]), "r"(a[3]), "r"(b0), "r"(b1));
}

// ---------------- big fp16 GEMM: C[M,1024] = A[M,1024] @ BT^T ----------------
// A fp16 row-major [M,1024]; BT fp16 [N=1024][K=1024] (pre-transposed weights).
// C fp32 (+bias)(+res)(opt tf32 round). 128x128 CTA tile; 8 warps 4(m)x2(n),
// warp tile 32x64; BK=32 (2 x k16); 2-stage cp.async (R7-proven loop shape).
__global__ __launch_bounds__(256)
void gemm_h_kernel(const __half* __restrict__ A, const __half* __restrict__ BT,
                   const float* __restrict__ bias, const float* __restrict__ res,
                   float* __restrict__ C, int roundOut)
{
    constexpr int RS = 40;                  // halves per smem row (80 B)
    __shared__ __half As[2][128 * RS];
    __shared__ __half Bs[2][128 * RS];

    const int tid = threadIdx.x, warp = tid >> 5, lane = tid & 31;
    const int wm = warp & 3, wn = warp >> 2;         // 4 x 2 warp grid
    const int gid = lane >> 2, tig = lane & 3;
    const int blockM = blockIdx.y * 128, blockN = blockIdx.x * 128;

    const int a_row = tid >> 2;             // 0..63, 2 passes
    const int a_col = (tid & 3) * 8;        // halves (16B chunks)

    auto loadStage = [&](int kt, int s) {
        #pragma unroll
        for (int p = 0; p < 2; p++) {
            const int rr = a_row + p * 64;
            cp_async16(&As[s][rr * RS + a_col],
                       A + (long long)(blockM + rr) * 1024 + kt * 32 + a_col);
            cp_async16(&Bs[s][rr * RS + a_col],
                       BT + (long long)(blockN + rr) * 1024 + kt * 32 + a_col);
        }
        cp_commit();
    };

    float acc[2][8][4];
    #pragma unroll
    for (int mi = 0; mi < 2; mi++)
        #pragma unroll
        for (int ni = 0; ni < 8; ni++)
            #pragma unroll
            for (int r = 0; r < 4; r++) acc[mi][ni][r] = 0.f;

    loadStage(0, 0);
    for (int kt = 0; kt < 32; kt++) {
        const int s = kt & 1;
        if (kt + 1 < 32) { loadStage(kt + 1, s ^ 1); cp_wait<1>(); }
        else             { cp_wait<0>(); }
        __syncthreads();

        #pragma unroll
        for (int ks = 0; ks < 2; ks++) {
            const int kb = ks * 16;
            uint32_t af[2][4], bf[8][2];
            #pragma unroll
            for (int mi = 0; mi < 2; mi++) {
                const int r0 = wm * 32 + mi * 16 + gid;
                const int base = r0 * RS + kb + tig * 2;
                af[mi][0] = *reinterpret_cast<const uint32_t*>(&As[s][base]);
                af[mi][1] = *reinterpret_cast<const uint32_t*>(&As[s][base + 8 * RS]);
                af[mi][2] = *reinterpret_cast<const uint32_t*>(&As[s][base + 8]);
                af[mi][3] = *reinterpret_cast<const uint32_t*>(&As[s][base + 8 * RS + 8]);
            }
            #pragma unroll
            for (int ni = 0; ni < 8; ni++) {
                const int n0 = wn * 64 + ni * 8 + gid;
                const int base = n0 * RS + kb + tig * 2;
                bf[ni][0] = *reinterpret_cast<const uint32_t*>(&Bs[s][base]);
                bf[ni][1] = *reinterpret_cast<const uint32_t*>(&Bs[s][base + 8]);
            }
            #pragma unroll
            for (int mi = 0; mi < 2; mi++)
                #pragma unroll
                for (int ni = 0; ni < 8; ni++)
                    mma_f16(acc[mi][ni], af[mi], bf[ni][0], bf[ni][1]);
        }
        __syncthreads();
    }

    // epilogue (identical layout to tf32 version)
    #pragma unroll
    for (int mi = 0; mi < 2; mi++)
        #pragma unroll
        for (int ni = 0; ni < 8; ni++) {
            const int gr0 = blockM + wm * 32 + mi * 16 + gid;
            const int gc  = blockN + wn * 64 + ni * 8 + tig * 2;
            const float bx = bias[gc], by = bias[gc + 1];
            #pragma unroll
            for (int half_ = 0; half_ < 2; half_++) {
                const int gr = gr0 + half_ * 8;
                float v0 = acc[mi][ni][half_ * 2 + 0] + bx;
                float v1 = acc[mi][ni][half_ * 2 + 1] + by;
                const long long off = (long long)gr * 1024 + gc;
                if (res) { v0 += res[off]; v1 += res[off + 1]; }
                if (roundOut) { v0 = tf32r(v0); v1 = tf32r(v1); }
                float2 o; o.x = v0; o.y = v1;
                *reinterpret_cast<float2*>(C + off) = o;
            }
        }
}

// ---------------- generic batched-strided tf32 GEMM (k/v proj; R7-proven) ---
template<int BM, int BN, int WM, int WN>
__global__ __launch_bounds__(256)
void gemm_tf32_kernel(const float* __restrict__ A, const float* __restrict__ B,
                      float* __restrict__ C, const float* __restrict__ bias,
                      const float* __restrict__ res,
                      int M, int N, int K, int lda, int ldb, int ldc,
                      long long sAo, long long sAi, long long sBo, long long sBi,
                      long long sCo, long long sCi, int nInner, int roundOut)
{
    constexpr int BK = 16;
    constexpr int WTM = BM / WM, WTN = BN / WN;
    constexpr int MI = WTM / 16, NI = WTN / 8;

    __shared__ float As[2][BM][BK + 4];
    __shared__ float Bs[2][BK][BN + 8];

    const int z = blockIdx.z;
    const int outer = z / nInner, inner = z - outer * nInner;
    A += outer * sAo + inner * sAi;
    B += outer * sBo + inner * sBi;
    C += outer * sCo + inner * sCi;
    if (res) res += outer * sCo + inner * sCi;

    const int tid = threadIdx.x;
    const int warp = tid >> 5, lane = tid & 31;
    const int wm = warp % WM, wn = warp / WM;
    const int gid = lane >> 2, tig = lane & 3;
    const int blockM = blockIdx.y * BM, blockN = blockIdx.x * BN;

    const int a_row = tid >> 2;
    const int a_col = (tid & 3) << 2;
    constexpr int B_COLS4 = BN / 4;
    constexpr int B_RPP = 256 / B_COLS4;
    constexpr int B_PASSES = BK / B_RPP;
    const int b_row = tid / B_COLS4;
    const int b_col = (tid % B_COLS4) << 2;

    const float* Ab = A + (long long)blockM * lda;
    const float* Bb = B + blockN;

    auto loadStage = [&](int kt, int s) {
        const float* Ag = Ab + kt * BK;
        #pragma unroll
        for (int p = 0; p < 2; p++) {
            int rr = a_row + p * 64;
            cp_async16(&As[s][rr][a_col], Ag + (long long)rr * lda + a_col);
        }
        const float* Bg = Bb + (long long)(kt * BK) * ldb;
        #pragma unroll
        for (int p = 0; p < B_PASSES; p++) {
            int rr = b_row + p * B_RPP;
            cp_async16(&Bs[s][rr][b_col], Bg + (long long)rr * ldb + b_col);
        }
        cp_commit();
    };

    float acc[MI][NI][4];
    #pragma unroll
    for (int mi = 0; mi < MI; mi++)
        #pragma unroll
        for (int ni = 0; ni < NI; ni++)
            #pragma unroll
            for (int rr = 0; rr < 4; rr++) acc[mi][ni][rr] = 0.f;

    const int KT = K / BK;
    const int wrow = wm * WTM, wcol = wn * WTN;

    loadStage(0, 0);
    for (int kt = 0; kt < KT; kt++) {
        const int s = kt & 1;
        if (kt + 1 < KT) { loadStage(kt + 1, s ^ 1); cp_wait<1>(); }
        else             { cp_wait<0>(); }
        __syncthreads();

        #pragma unroll
        for (int ks = 0; ks < 2; ks++) {
            float af[MI][4], bf[NI][2];
            #pragma unroll
            for (int mi = 0; mi < MI; mi++) {
                const int r0 = wrow + mi * 16 + gid, c0 = ks * 8 + tig;
                af[mi][0] = As[s][r0    ][c0    ];
                af[mi][1] = As[s][r0 + 8][c0    ];
                af[mi][2] = As[s][r0    ][c0 + 4];
                af[mi][3] = As[s][r0 + 8][c0 + 4];
            }
            #pragma unroll
            for (int ni = 0; ni < NI; ni++) {
                const int c0 = wcol + ni * 8 + gid, r0 = ks * 8 + tig;
                bf[ni][0] = Bs[s][r0    ][c0];
                bf[ni][1] = Bs[s][r0 + 4][c0];
            }
            #pragma unroll
            for (int mi = 0; mi < MI; mi++)
                #pragma unroll
                for (int ni = 0; ni < NI; ni++)
                    mma_tf32(acc[mi][ni], af[mi], bf[ni]);
        }
        __syncthreads();
    }

    #pragma unroll
    for (int mi = 0; mi < MI; mi++)
        #pragma unroll
        for (int ni = 0; ni < NI; ni++) {
            const int gr0 = blockM + wrow + mi * 16 + gid;
            const int gc  = blockN + wcol + ni * 8 + tig * 2;
            float bx = 0.f, by = 0.f;
            if (bias) { bx = bias[gc]; by = bias[gc + 1]; }
            #pragma unroll
            for (int half_ = 0; half_ < 2; half_++) {
                const int gr = gr0 + half_ * 8;
                float v0 = acc[mi][ni][half_ * 2 + 0] + bx;
                float v1 = acc[mi][ni][half_ * 2 + 1] + by;
                const long long off = (long long)gr * ldc + gc;
                if (res) { v0 += res[off]; v1 += res[off + 1]; }
                if (roundOut) { v0 = tf32r(v0); v1 = tf32r(v1); }
                float2 o; o.x = v0; o.y = v1;
                *reinterpret_cast<float2*>(C + off) = o;
            }
        }
}

// ---------------- fused flash cross-attention (proven, unchanged) -----------
__global__ __launch_bounds__(256)
void flash_kernel(const float* __restrict__ q, const float* __restrict__ k,
                  const float* __restrict__ v, float* __restrict__ y)
{
    extern __shared__ float smf[];
    float* Qs = smf;
    float* Ks = Qs + 128 * 68;
    float* Vs = Ks + 128 * 68;
    float* Ps = Vs + 128 * 68;

    const int tb = blockIdx.x;
    const int bh = blockIdx.y;
    const int b = bh >> 4, h = bh & 15;
    const int tid = threadIdx.x, warp = tid >> 5, lane = tid & 31;
    const int gid = lane >> 2, tig = lane & 3;
    const int wrow = warp * 16;

    const float* qg = q + ((long long)(b * 4096 + tb * 128)) * 1024 + h * 64;
    const float* kg = k + ((long long)(b * 256)) * 1024 + h * 64;
    const float* vg = v + ((long long)(b * 256)) * 1024 + h * 64;

    const int lr = tid >> 4;
    const int lc = (tid & 15) << 2;

    #pragma unroll
    for (int p = 0; p < 8; p++)
        cp_async16(&Qs[(lr + p * 16) * 68 + lc], qg + (long long)(lr + p * 16) * 1024 + lc);
    #pragma unroll
    for (int p = 0; p < 8; p++)
        cp_async16(&Ks[(lr + p * 16) * 68 + lc], kg + (long long)(lr + p * 16) * 1024 + lc);
    #pragma unroll
    for (int p = 0; p < 8; p++)
        cp_async16(&Vs[(lr + p * 16) * 68 + lc], vg + (long long)(lr + p * 16) * 1024 + lc);
    cp_commit();

    float oacc[8][4];
    #pragma unroll
    for (int i = 0; i < 8; i++) { oacc[i][0] = oacc[i][1] = oacc[i][2] = oacc[i][3] = 0.f; }
    float m0 = -1e30f, m1 = -1e30f, l0 = 0.f, l1 = 0.f;

    #pragma unroll
    for (int kb = 0; kb < 2; kb++) {
        cp_wait<0>();
        __syncthreads();

        float sacc[16][4];
        #pragma unroll
        for (int i = 0; i < 16; i++) { sacc[i][0] = sacc[i][1] = sacc[i][2] = sacc[i][3] = 0.f; }
        #pragma unroll
        for (int ks = 0; ks < 8; ks++) {
            float a[4];
            a[0] = Qs[(wrow + gid    ) * 68 + ks * 8 + tig    ];
            a[1] = Qs[(wrow + gid + 8) * 68 + ks * 8 + tig    ];
            a[2] = Qs[(wrow + gid    ) * 68 + ks * 8 + tig + 4];
            a[3] = Qs[(wrow + gid + 8) * 68 + ks * 8 + tig + 4];
            #pragma unroll
            for (int ni = 0; ni < 16; ni++) {
                float bb[2];
                bb[0] = Ks[(ni * 8 + gid) * 68 + ks * 8 + tig    ];
                bb[1] = Ks[(ni * 8 + gid) * 68 + ks * 8 + tig + 4];
                mma_tf32(sacc[ni], a, bb);
            }
        }

        float rm0 = -1e30f, rm1 = -1e30f;
        #pragma unroll
        for (int ni = 0; ni < 16; ni++) {
            sacc[ni][0] *= 0.125f; sacc[ni][1] *= 0.125f;
            sacc[ni][2] *= 0.125f; sacc[ni][3] *= 0.125f;
            rm0 = fmaxf(rm0, fmaxf(sacc[ni][0], sacc[ni][1]));
            rm1 = fmaxf(rm1, fmaxf(sacc[ni][2], sacc[ni][3]));
        }
        rm0 = fmaxf(rm0, __shfl_xor_sync(0xffffffffu, rm0, 1));
        rm0 = fmaxf(rm0, __shfl_xor_sync(0xffffffffu, rm0, 2));
        rm1 = fmaxf(rm1, __shfl_xor_sync(0xffffffffu, rm1, 1));
        rm1 = fmaxf(rm1, __shfl_xor_sync(0xffffffffu, rm1, 2));
        const float mn0 = fmaxf(m0, rm0), mn1 = fmaxf(m1, rm1);
        const float al0 = __expf(m0 - mn0), al1 = __expf(m1 - mn1);
        float ps0 = 0.f, ps1 = 0.f;
        #pragma unroll
        for (int ni = 0; ni < 16; ni++) {
            float p00 = __expf(sacc[ni][0] - mn0);
            float p01 = __expf(sacc[ni][1] - mn0);
            float p10 = __expf(sacc[ni][2] - mn1);
            float p11 = __expf(sacc[ni][3] - mn1);
            ps0 += p00 + p01; ps1 += p10 + p11;
            float2 w0; w0.x = tf32r(p00); w0.y = tf32r(p01);
            float2 w1; w1.x = tf32r(p10); w1.y = tf32r(p11);
            *reinterpret_cast<float2*>(&Ps[(wrow + gid    ) * 132 + ni * 8 + tig * 2]) = w0;
            *reinterpret_cast<float2*>(&Ps[(wrow + gid + 8) * 132 + ni * 8 + tig * 2]) = w1;
        }
        ps0 += __shfl_xor_sync(0xffffffffu, ps0, 1);
        ps0 += __shfl_xor_sync(0xffffffffu, ps0, 2);
        ps1 += __shfl_xor_sync(0xffffffffu, ps1, 1);
        ps1 += __shfl_xor_sync(0xffffffffu, ps1, 2);
        l0 = l0 * al0 + ps0;  l1 = l1 * al1 + ps1;
        m0 = mn0;  m1 = mn1;
        #pragma unroll
        for (int i = 0; i < 8; i++) {
            oacc[i][0] *= al0; oacc[i][1] *= al0;
            oacc[i][2] *= al1; oacc[i][3] *= al1;
        }
        __syncthreads();

        if (kb == 0) {
            #pragma unroll
            for (int p = 0; p < 8; p++)
                cp_async16(&Ks[(lr + p * 16) * 68 + lc],
                           kg + (long long)(128 + lr + p * 16) * 1024 + lc);
            cp_commit();
        }

        #pragma unroll
        for (int ks = 0; ks < 16; ks++) {
            float a[4];
            a[0] = Ps[(wrow + gid    ) * 132 + ks * 8 + tig    ];
            a[1] = Ps[(wrow + gid + 8) * 132 + ks * 8 + tig    ];
            a[2] = Ps[(wrow + gid    ) * 132 + ks * 8 + tig + 4];
            a[3] = Ps[(wrow + gid + 8) * 132 + ks * 8 + tig + 4];
            #pragma unroll
            for (int ni = 0; ni < 8; ni++) {
                float bb[2];
                bb[0] = Vs[(ks * 8 + tig    ) * 68 + ni * 8 + gid];
                bb[1] = Vs[(ks * 8 + tig + 4) * 68 + ni * 8 + gid];
                mma_tf32(oacc[ni], a, bb);
            }
        }
        __syncthreads();

        if (kb == 0) {
            #pragma unroll
            for (int p = 0; p < 8; p++)
                cp_async16(&Vs[(lr + p * 16) * 68 + lc],
                           vg + (long long)(128 + lr + p * 16) * 1024 + lc);
            cp_commit();
        }
    }

    const float inv0 = 1.f / l0, inv1 = 1.f / l1;
    float* yg = y + ((long long)(b * 4096 + tb * 128 + wrow)) * 1024 + h * 64;
    #pragma unroll
    for (int ni = 0; ni < 8; ni++) {
        float2 w0; w0.x = oacc[ni][0] * inv0; w0.y = oacc[ni][1] * inv0;
        float2 w1; w1.x = oacc[ni][2] * inv1; w1.y = oacc[ni][3] * inv1;
        *reinterpret_cast<float2*>(&yg[(long long)gid * 1024 + ni * 8 + tig * 2]) = w0;
        *reinterpret_cast<float2*>(&yg[(long long)(gid + 8) * 1024 + ni * 8 + tig * 2]) = w1;
    }
}

// ---------------- LayerNorm (generic fp32 out; used for xf) ----------------
__global__ void ln_kernel(const float* __restrict__ X, float* __restrict__ Y,
                          const float* __restrict__ gam, const float* __restrict__ bet,
                          int Dlen, int roundOut)
{
    const int row = blockIdx.x;
    const float4* x4 = reinterpret_cast<const float4*>(X + (long long)row * Dlen);
    float4* y4 = reinterpret_cast<float4*>(Y + (long long)row * Dlen);
    const int nv = Dlen >> 2;
    const int tid = threadIdx.x, lane = tid & 31, warp = tid >> 5;

    float s = 0.f, ss = 0.f;
    for (int i = tid; i < nv; i += 256) {
        float4 v = x4[i];
        s  += v.x + v.y + v.z + v.w;
        ss += v.x*v.x + v.y*v.y + v.z*v.z + v.w*v.w;
    }
    #pragma unroll
    for (int o = 16; o > 0; o >>= 1) {
        s  += __shfl_xor_sync(0xffffffffu, s, o);
        ss += __shfl_xor_sync(0xffffffffu, ss, o);
    }
    __shared__ float rs[8], rss[8], stat[2];
    if (lane == 0) { rs[warp] = s; rss[warp] = ss; }
    __syncthreads();
    if (tid == 0) {
        float ts = 0.f, tss = 0.f;
        #pragma unroll
        for (int w = 0; w < 8; w++) { ts += rs[w]; tss += rss[w]; }
        const float mu = ts / (float)Dlen;
        const float var = tss / (float)Dlen - mu * mu;
        stat[0] = mu; stat[1] = rsqrtf(var + 1e-5f);
    }
    __syncthreads();
    const float mu = stat[0], rstd = stat[1];
    const float4* g4 = reinterpret_cast<const float4*>(gam);
    const float4* b4 = reinterpret_cast<const float4*>(bet);
    for (int i = tid; i < nv; i += 256) {
        float4 v = x4[i], g = g4[i], b = b4[i];
        v.x = (v.x - mu) * rstd * g.x + b.x;
        v.y = (v.y - mu) * rstd * g.y + b.y;
        v.z = (v.z - mu) * rstd * g.z + b.z;
        v.w = (v.w - mu) * rstd * g.w + b.w;
        if (roundOut) { v.x=tf32r(v.x); v.y=tf32r(v.y); v.z=tf32r(v.z); v.w=tf32r(v.w); }
        y4[i] = v;
    }
}

// ---------------- LN(x) -> fp16 (row = 1024) ----------------
__global__ void ln_half_kernel(const float* __restrict__ X,
                               const float* __restrict__ gam, const float* __restrict__ bet,
                               __half* __restrict__ Y)
{
    const int row = blockIdx.x;
    const float4* x4 = reinterpret_cast<const float4*>(X + (long long)row * 1024);
    const int tid = threadIdx.x, lane = tid & 31, warp = tid >> 5;

    float4 v = x4[tid];
    float s  = v.x + v.y + v.z + v.w;
    float ss = v.x*v.x + v.y*v.y + v.z*v.z + v.w*v.w;
    #pragma unroll
    for (int o = 16; o > 0; o >>= 1) {
        s  += __shfl_xor_sync(0xffffffffu, s, o);
        ss += __shfl_xor_sync(0xffffffffu, ss, o);
    }
    __shared__ float rs[8], rss[8], stat[2];
    if (lane == 0) { rs[warp] = s; rss[warp] = ss; }
    __syncthreads();
    if (tid == 0) {
        float ts = 0.f, tss = 0.f;
        #pragma unroll
        for (int w = 0; w < 8; w++) { ts += rs[w]; tss += rss[w]; }
        const float mu = ts * (1.f / 1024.f);
        const float var = tss * (1.f / 1024.f) - mu * mu;
        stat[0] = mu; stat[1] = rsqrtf(var + 1e-5f);
    }
    __syncthreads();
    const float mu = stat[0], rstd = stat[1];
    const float4 g  = reinterpret_cast<const float4*>(gam)[tid];
    const float4 bb = reinterpret_cast<const float4*>(bet)[tid];
    __half2 h0 = __floats2half2_rn((v.x - mu) * rstd * g.x + bb.x,
                                   (v.y - mu) * rstd * g.y + bb.y);
    __half2 h1 = __floats2half2_rn((v.z - mu) * rstd * g.z + bb.z,
                                   (v.w - mu) * rstd * g.w + bb.w);
    __half2* Y2 = reinterpret_cast<__half2*>(Y + (long long)row * 1024);
    Y2[2 * tid] = h0;  Y2[2 * tid + 1] = h1;
}

// ---------------- AdaLN modulate + SiLU -> fp16 ----------------
__global__ void modulate_half_kernel(const float* __restrict__ Yin, const float* __restrict__ eo,
                                     const float* __restrict__ gam, const float* __restrict__ bet,
                                     __half* __restrict__ Out)
{
    const int row = blockIdx.x, b = row >> 12;
    const float4* x4 = reinterpret_cast<const float4*>(Yin + (long long)row * 1024);
    const int tid = threadIdx.x, lane = tid & 31, warp = tid >> 5;

    float4 v = x4[tid];
    float s  = v.x + v.y + v.z + v.w;
    float ss = v.x*v.x + v.y*v.y + v.z*v.z + v.w*v.w;
    #pragma unroll
    for (int o = 16; o > 0; o >>= 1) {
        s  += __shfl_xor_sync(0xffffffffu, s, o);
        ss += __shfl_xor_sync(0xffffffffu, ss, o);
    }
    __shared__ float rs[8], rss[8], stat[2];
    if (lane == 0) { rs[warp] = s; rss[warp] = ss; }
    __syncthreads();
    if (tid == 0) {
        float ts = 0.f, tss = 0.f;
        #pragma unroll
        for (int w = 0; w < 8; w++) { ts += rs[w]; tss += rss[w]; }
        const float mu = ts * (1.f / 1024.f);
        const float var = tss * (1.f / 1024.f) - mu * mu;
        stat[0] = mu; stat[1] = rsqrtf(var + 1e-5f);
    }
    __syncthreads();
    const float mu = stat[0], rstd = stat[1];
    const float4 g  = reinterpret_cast<const float4*>(gam)[tid];
    const float4 bb = reinterpret_cast<const float4*>(bet)[tid];
    const float4 sc = reinterpret_cast<const float4*>(eo + b * 2048)[tid];
    const float4 sh = reinterpret_cast<const float4*>(eo + b * 2048 + 1024)[tid];
    float o0 = silu_f(((v.x-mu)*rstd*g.x + bb.x) * (1.f+sc.x) + sh.x);
    float o1 = silu_f(((v.y-mu)*rstd*g.y + bb.y) * (1.f+sc.y) + sh.y);
    float o2 = silu_f(((v.z-mu)*rstd*g.z + bb.z) * (1.f+sc.z) + sh.z);
    float o3 = silu_f(((v.w-mu)*rstd*g.w + bb.w) * (1.f+sc.w) + sh.w);
    __half2* O2 = reinterpret_cast<__half2*>(Out + (long long)row * 1024);
    O2[2 * tid]     = __floats2half2_rn(o0, o1);
    O2[2 * tid + 1] = __floats2half2_rn(o2, o3);
}

// ---------------- weight fp32 [K][N] -> fp16 [N][K] transpose ---------------
__global__ void half_trans_kernel(const float* __restrict__ W, __half* __restrict__ WT) {
    __shared__ float t[32][33];
    const int bn = blockIdx.x * 32, bk = blockIdx.y * 32;
    const int tx = threadIdx.x, ty = threadIdx.y;
    #pragma unroll
    for (int i = ty; i < 32; i += 8)
        t[i][tx] = W[(long long)(bk + i) * 1024 + bn + tx];
    __syncthreads();
    #pragma unroll
    for (int i = ty; i < 32; i += 8)
        WT[(long long)(bn + i) * 1024 + bk + tx] = __float2half_rn(t[tx][i]);
}

// ---------------- small utility kernels ----------------
__global__ void tf32copy_kernel(const float* __restrict__ s, float* __restrict__ d, int n) {
    int i = blockIdx.x * 256 + threadIdx.x;
    if (i < n) d[i] = tf32r(s[i]);
}
__global__ void silu_emb_kernel(const float* __restrict__ e, float* __restrict__ se) {
    int i = blockIdx.x * 256 + threadIdx.x;
    if (i < 4096) se[i] = silu_f(e[i]);
}
__global__ void embgemm_kernel(const float* __restrict__ se, const float* __restrict__ We,
                               const float* __restrict__ be, float* __restrict__ eo)
{
    const int b = blockIdx.y;
    const int j = blockIdx.x * 256 + threadIdx.x;
    const float* s = se + b * 1024;
    float acc = 0.f;
    #pragma unroll 4
    for (int kk = 0; kk < 1024; kk++) acc += s[kk] * We[kk * 2048 + j];
    eo[b * 2048 + j] = acc + be[j];
}

// ---------------- host ----------------
static float* symf(const void* s) { void* p = nullptr; cudaGetSymbolAddress(&p, s); return (float*)p; }
static __half* symh(const void* s) { void* p = nullptr; cudaGetSymbolAddress(&p, s); return (__half*)p; }

extern "C" void kernel_launch(void* const* d_in, const int* in_sizes, int n_in,
                              void* d_out, int out_size)
{
    const float* x       = (const float*)d_in[0];
    const float* xf      = (const float*)d_in[1];
    const float* emb     = (const float*)d_in[2];
    const float* norm_g  = (const float*)d_in[3];
    const float* norm_b  = (const float*)d_in[4];
    const float* tnorm_g = (const float*)d_in[5];
    const float* tnorm_b = (const float*)d_in[6];
    const float* Wq      = (const float*)d_in[7];
    const float* bq      = (const float*)d_in[8];
    const float* Wk      = (const float*)d_in[9];
    const float* bk      = (const float*)d_in[10];
    const float* Wv      = (const float*)d_in[11];
    const float* bv      = (const float*)d_in[12];
    const float* We      = (const float*)d_in[13];
    const float* be      = (const float*)d_in[14];
    const float* snorm_g = (const float*)d_in[15];
    const float* snorm_b = (const float*)d_in[16];
    const float* Wo      = (const float*)d_in[17];
    const float* bo      = (const float*)d_in[18];
    float* out = (float*)d_out;

    __half* ah  = symh(d_ah);
    __half* wqh = symh(d_Wqh);
    __half* woh = symh(d_Woh);
    float* xfn = symf(d_xfn);
    float* q   = symf(d_q);   float* kbuf= symf(d_k);
    float* vbuf= symf(d_v);   float* y   = symf(d_y);
    float* eo  = symf(d_eo);  float* se  = symf(d_se);
    float* wk  = symf(d_Wk);  float* wv  = symf(d_Wv);

    const int FLASH_SMEM = (128 * 68 * 3 + 128 * 132) * 4;   // 172032 B
    cudaFuncSetAttribute(flash_kernel, cudaFuncAttributeMaxDynamicSharedMemorySize, FLASH_SMEM);

    // prep
    ln_half_kernel<<<16384, 256>>>(x, norm_g, norm_b, ah);
    ln_kernel<<<1024, 256>>>(xf, xfn, tnorm_g, tnorm_b, 768, 1);
    half_trans_kernel<<<dim3(32, 32), dim3(32, 8)>>>(Wq, wqh);
    half_trans_kernel<<<dim3(32, 32), dim3(32, 8)>>>(Wo, woh);
    tf32copy_kernel<<<3072, 256>>>(Wk, wk, 786432);
    tf32copy_kernel<<<3072, 256>>>(Wv, wv, 786432);
    silu_emb_kernel<<<16, 256>>>(emb, se);
    embgemm_kernel<<<dim3(8, 4), 256>>>(se, We, be, eo);

    // q = LN(x)@Wq + bq  (fp16 HMMA, tf32-rounded out for flash)
    gemm_h_kernel<<<dim3(8, 128), 256>>>(ah, wqh, bq, nullptr, q, 1);

    // k,v = LN(xf)@Wk/Wv + b  (SIMT tf32, small)
    gemm_tf32_kernel<128,128,4,2><<<dim3(8, 8, 1), 256>>>(
        xfn, wk, kbuf, bk, nullptr, 1024, 1024, 768, 768, 1024, 1024,
        0, 0, 0, 0, 0, 0, 1, 1);
    gemm_tf32_kernel<128,128,4,2><<<dim3(8, 8, 1), 256>>>(
        xfn, wv, vbuf, bv, nullptr, 1024, 1024, 768, 768, 1024, 1024,
        0, 0, 0, 0, 0, 0, 1, 1);

    // fused attention: y = softmax(q k^T / 8) v
    flash_kernel<<<dim3(32, 64), 256, FLASH_SMEM>>>(q, kbuf, vbuf, y);

    // g = fp16(silu(LN(y)*(1+scale)+shift))  (reuse ah)
    modulate_half_kernel<<<16384, 256>>>(y, eo, snorm_g, snorm_b, ah);

    // out = x + g@Wo + bo  (fp16 HMMA, fused residual)
    gemm_h_kernel<<<dim3(8, 128), 256>>>(ah, woh, bo, x, out, 0);
}